// round 11
// baseline (speedup 1.0000x reference)
#include <cuda_runtime.h>
#include <cstdint>

#define MAXN 100000
#define MAXE 1600000

// ---------------- scratch (device globals; no allocs allowed) ----------------
__device__ float g_m[MAXN * 64];      // pool-transformed features
__device__ float g_agg[MAXN * 64];    // aggregated features
__device__ float g_h1[MAXN * 64];     // layer-1 output
__device__ float g_h2[MAXN * 32];     // layer-2 output
__device__ float g_agg3[MAXN * 32];   // layer-3 mean aggregate
__device__ int   g_rowptr[MAXN + 1];
__device__ int   g_deg[MAXN];         // degree, then reused as scatter cursor
__device__ int   g_scantmp[MAXN];
__device__ int   g_bsum[1024];
__device__ int   g_csrc[MAXE];        // CSR src ids, grouped by dst

// ---------------- f32x2 packed-FMA helpers (sm_100+) ----------------
__device__ __forceinline__ unsigned long long pk2(float lo, float hi) {
    unsigned long long r;
    asm("mov.b64 %0,{%1,%2};" : "=l"(r) : "f"(lo), "f"(hi));
    return r;
}
__device__ __forceinline__ void fma2(unsigned long long& d, unsigned long long a,
                                     unsigned long long b) {
    asm("fma.rn.f32x2 %0, %1, %2, %0;" : "+l"(d) : "l"(a), "l"(b));
}
__device__ __forceinline__ void upk2(unsigned long long v, float& lo, float& hi) {
    asm("mov.b64 {%0,%1},%2;" : "=f"(lo), "=f"(hi) : "l"(v));
}

// ---------------- CSR build ----------------
__global__ void k_hist(const int* __restrict__ dst, int* __restrict__ deg, int E, int N) {
    int i = blockIdx.x * blockDim.x + threadIdx.x;
    int e = i * 4;
    if (e + 3 < E) {
        int4 d4 = *reinterpret_cast<const int4*>(&dst[e]);
        if (d4.x >= 0 && d4.x < N) atomicAdd(&deg[d4.x], 1);
        if (d4.y >= 0 && d4.y < N) atomicAdd(&deg[d4.y], 1);
        if (d4.z >= 0 && d4.z < N) atomicAdd(&deg[d4.z], 1);
        if (d4.w >= 0 && d4.w < N) atomicAdd(&deg[d4.w], 1);
    } else {
        for (int k = e; k < E; k++) {
            int d = dst[k];
            if (d >= 0 && d < N) atomicAdd(&deg[d], 1);
        }
    }
}

__global__ void k_scan1(const int* __restrict__ deg, int* __restrict__ scantmp,
                        int* __restrict__ bsum, int n) {
    __shared__ int sh[512];
    int tid = threadIdx.x;
    int i = blockIdx.x * 512 + tid;
    int v = (i < n) ? deg[i] : 0;
    sh[tid] = v;
    __syncthreads();
#pragma unroll
    for (int off = 1; off < 512; off <<= 1) {
        int t = (tid >= off) ? sh[tid - off] : 0;
        __syncthreads();
        sh[tid] += t;
        __syncthreads();
    }
    if (i < n) scantmp[i] = sh[tid];
    if (tid == 511) bsum[blockIdx.x] = sh[511];
}

__global__ void k_scan2(int* bsum, int nb) {
    __shared__ int sh[256];
    int tid = threadIdx.x;
    int v = (tid < nb) ? bsum[tid] : 0;
    sh[tid] = v;
    __syncthreads();
#pragma unroll
    for (int off = 1; off < 256; off <<= 1) {
        int t = (tid >= off) ? sh[tid - off] : 0;
        __syncthreads();
        sh[tid] += t;
        __syncthreads();
    }
    if (tid < nb) bsum[tid] = sh[tid] - v;  // exclusive
}

__global__ void k_scan3(const int* __restrict__ scantmp, int* __restrict__ deg_cursor,
                        int* __restrict__ rowptr, const int* __restrict__ bsum,
                        int n, int E) {
    int i = blockIdx.x * blockDim.x + threadIdx.x;
    if (i < n) {
        int d = deg_cursor[i];
        int ex = scantmp[i] - d + bsum[i >> 9];
        rowptr[i] = ex;
        deg_cursor[i] = ex;   // cursor
    }
    if (i == 0) rowptr[n] = E;
}

__global__ void k_scatter(const int* __restrict__ src, const int* __restrict__ dst,
                          int* __restrict__ cursor, int* __restrict__ csrc, int E, int N) {
    int i = blockIdx.x * blockDim.x + threadIdx.x;
    int e = i * 4;
    if (e + 3 < E) {
        int4 s4 = *reinterpret_cast<const int4*>(&src[e]);
        int4 d4 = *reinterpret_cast<const int4*>(&dst[e]);
        if (d4.x >= 0 && d4.x < N) csrc[atomicAdd(&cursor[d4.x], 1)] = s4.x;
        if (d4.y >= 0 && d4.y < N) csrc[atomicAdd(&cursor[d4.y], 1)] = s4.y;
        if (d4.z >= 0 && d4.z < N) csrc[atomicAdd(&cursor[d4.z], 1)] = s4.z;
        if (d4.w >= 0 && d4.w < N) csrc[atomicAdd(&cursor[d4.w], 1)] = s4.w;
    } else {
        for (int k = e; k < E; k++) {
            int d = dst[k];
            if (d >= 0 && d < N) csrc[atomicAdd(&cursor[d], 1)] = src[k];
        }
    }
}

// ---------------- aggregation (gather over CSR, warp per node) ----------------
__global__ void k_agg_max64(const float4* __restrict__ feat4, float4* __restrict__ out4,
                            const int* __restrict__ rowptr, const int* __restrict__ srcs,
                            int n) {
    int v = blockIdx.x * (blockDim.x >> 5) + (threadIdx.x >> 5);
    if (v >= n) return;
    int lane = threadIdx.x & 31;
    int half = lane >> 4, sub = lane & 15;
    int beg = rowptr[v], end = rowptr[v + 1];
    float4 a = make_float4(0.f, 0.f, 0.f, 0.f);
#pragma unroll 4
    for (int e = beg + half; e < end; e += 2) {
        int s = __ldg(&srcs[e]);
        float4 t = feat4[(size_t)s * 16 + sub];
        a.x = fmaxf(a.x, t.x);
        a.y = fmaxf(a.y, t.y);
        a.z = fmaxf(a.z, t.z);
        a.w = fmaxf(a.w, t.w);
    }
    a.x = fmaxf(a.x, __shfl_xor_sync(0xffffffffu, a.x, 16));
    a.y = fmaxf(a.y, __shfl_xor_sync(0xffffffffu, a.y, 16));
    a.z = fmaxf(a.z, __shfl_xor_sync(0xffffffffu, a.z, 16));
    a.w = fmaxf(a.w, __shfl_xor_sync(0xffffffffu, a.w, 16));
    if (half == 0) out4[(size_t)v * 16 + sub] = a;
}

__global__ void k_agg_mean32(const float4* __restrict__ feat4, float4* __restrict__ out4,
                             const int* __restrict__ rowptr, const int* __restrict__ srcs,
                             int n) {
    int v = blockIdx.x * (blockDim.x >> 5) + (threadIdx.x >> 5);
    if (v >= n) return;
    int lane = threadIdx.x & 31;
    int q = lane >> 3, sub = lane & 7;
    int beg = rowptr[v], end = rowptr[v + 1];
    float4 a = make_float4(0.f, 0.f, 0.f, 0.f);
#pragma unroll 4
    for (int e = beg + q; e < end; e += 4) {
        int s = __ldg(&srcs[e]);
        float4 t = feat4[(size_t)s * 8 + sub];
        a.x += t.x; a.y += t.y; a.z += t.z; a.w += t.w;
    }
#pragma unroll
    for (int off = 8; off <= 16; off <<= 1) {
        a.x += __shfl_xor_sync(0xffffffffu, a.x, off);
        a.y += __shfl_xor_sync(0xffffffffu, a.y, off);
        a.z += __shfl_xor_sync(0xffffffffu, a.z, off);
        a.w += __shfl_xor_sync(0xffffffffu, a.w, off);
    }
    if (q == 0) {
        float cnt = (float)(end - beg);
        float inv = 1.f / fmaxf(cnt, 1.f);
        a.x *= inv; a.y *= inv; a.z *= inv; a.w *= inv;
        out4[(size_t)v * 8 + sub] = a;
    }
}

// ---------------- dual-output node GEMM ----------------
// Reads A once; produces out1 = relu(A@W1 + b1)  [OUT1]
//                    and out2 =      A@W2 + b2   [OUT2]
// 256 threads, 64 nodes/block, 2 nodes x (TJ1+TJ2) outs per thread.
template <int IN, int OUT1, int OUT2>
__global__ void __launch_bounds__(256, 3) k_gemm_dual(const float4* __restrict__ A4,
                                                      const float* __restrict__ W1,
                                                      const float* __restrict__ b1,
                                                      float* __restrict__ out1,
                                                      const float* __restrict__ W2,
                                                      const float* __restrict__ b2,
                                                      float* __restrict__ out2, int n) {
    constexpr int NPB = 64;
    constexpr int TJ1 = OUT1 / 8, NP1 = TJ1 / 2;
    constexpr int TJ2 = OUT2 / 8, NP2 = TJ2 / 2;
    constexpr int V = IN / 4;
    extern __shared__ float sm[];
    float* sW1 = sm;                       // IN*OUT1
    float* sW2 = sm + IN * OUT1;           // IN*OUT2
    float* sB1 = sW2 + IN * OUT2;          // OUT1
    float* sB2 = sB1 + OUT1;               // OUT2

    int tid = threadIdx.x;
    for (int i = tid; i < IN * OUT1; i += 256) sW1[i] = W1[i];
    for (int i = tid; i < IN * OUT2; i += 256) sW2[i] = W2[i];
    for (int i = tid; i < OUT1; i += 256) sB1[i] = b1[i];
    for (int i = tid; i < OUT2; i += 256) sB2[i] = b2[i];
    __syncthreads();

    int jg = tid & 7;
    int ng = tid >> 3;                 // 0..31, each owns 2 nodes
    int n0 = blockIdx.x * NPB + ng * 2;

    unsigned long long acc1[2][NP1], acc2[2][NP2];
#pragma unroll
    for (int i = 0; i < 2; i++) {
#pragma unroll
        for (int j = 0; j < NP1; j++) acc1[i][j] = 0ull;
#pragma unroll
        for (int j = 0; j < NP2; j++) acc2[i][j] = 0ull;
    }

    for (int kq = 0; kq < IN; kq += 4) {
        float4 xv[2];
#pragma unroll
        for (int i = 0; i < 2; i++)
            xv[i] = (n0 + i < n) ? __ldg(&A4[(size_t)(n0 + i) * V + (kq >> 2)])
                                 : make_float4(0.f, 0.f, 0.f, 0.f);
#pragma unroll
        for (int h = 0; h < 2; h++) {
            unsigned long long w1a[NP1], w1b[NP1], w2a[NP2], w2b[NP2];
#pragma unroll
            for (int p = 0; p < NP1; p += 2) {
                float4 w = *reinterpret_cast<const float4*>(
                    &sW1[(kq + 2 * h) * OUT1 + jg * TJ1 + 2 * p]);
                w1a[p] = pk2(w.x, w.y);
                if (p + 1 < NP1) w1a[p + 1] = pk2(w.z, w.w);
            }
#pragma unroll
            for (int p = 0; p < NP1; p += 2) {
                float4 w = *reinterpret_cast<const float4*>(
                    &sW1[(kq + 2 * h + 1) * OUT1 + jg * TJ1 + 2 * p]);
                w1b[p] = pk2(w.x, w.y);
                if (p + 1 < NP1) w1b[p + 1] = pk2(w.z, w.w);
            }
#pragma unroll
            for (int p = 0; p < NP2; p += 2) {
                float4 w = *reinterpret_cast<const float4*>(
                    &sW2[(kq + 2 * h) * OUT2 + jg * TJ2 + 2 * p]);
                w2a[p] = pk2(w.x, w.y);
                if (p + 1 < NP2) w2a[p + 1] = pk2(w.z, w.w);
            }
#pragma unroll
            for (int p = 0; p < NP2; p += 2) {
                float4 w = *reinterpret_cast<const float4*>(
                    &sW2[(kq + 2 * h + 1) * OUT2 + jg * TJ2 + 2 * p]);
                w2b[p] = pk2(w.x, w.y);
                if (p + 1 < NP2) w2b[p + 1] = pk2(w.z, w.w);
            }
#pragma unroll
            for (int i = 0; i < 2; i++) {
                float xlo = h ? xv[i].z : xv[i].x;
                float xhi = h ? xv[i].w : xv[i].y;
                unsigned long long a0 = pk2(xlo, xlo);
                unsigned long long a1 = pk2(xhi, xhi);
#pragma unroll
                for (int j = 0; j < NP1; j++) {
                    fma2(acc1[i][j], a0, w1a[j]);
                    fma2(acc1[i][j], a1, w1b[j]);
                }
#pragma unroll
                for (int j = 0; j < NP2; j++) {
                    fma2(acc2[i][j], a0, w2a[j]);
                    fma2(acc2[i][j], a1, w2b[j]);
                }
            }
        }
    }

#pragma unroll
    for (int i = 0; i < 2; i++) {
        int node = n0 + i;
        if (node < n) {
#pragma unroll
            for (int j = 0; j < NP1; j++) {
                float lo, hi;
                upk2(acc1[i][j], lo, hi);
                float v0 = fmaxf(lo + sB1[jg * TJ1 + 2 * j], 0.f);
                float v1 = fmaxf(hi + sB1[jg * TJ1 + 2 * j + 1], 0.f);
                *reinterpret_cast<float2*>(&out1[(size_t)node * OUT1 + jg * TJ1 + 2 * j]) =
                    make_float2(v0, v1);
            }
#pragma unroll
            for (int j = 0; j < NP2; j++) {
                float lo, hi;
                upk2(acc2[i][j], lo, hi);
                float v0 = lo + sB2[jg * TJ2 + 2 * j];
                float v1 = hi + sB2[jg * TJ2 + 2 * j + 1];
                *reinterpret_cast<float2*>(&out2[(size_t)node * OUT2 + jg * TJ2 + 2 * j]) =
                    make_float2(v0, v1);
            }
        }
    }
}

// ---------------- single GEMM (bias or RMW-add epilogue) ----------------
// !ADD: out = A@W + bias            ADD: out = [relu]( out + A@W )
template <int IN, int OUT, bool RELU, bool ADD>
__global__ void __launch_bounds__(256, 3) k_gemm(const float4* __restrict__ A4,
                                                 const float* __restrict__ W,
                                                 const float* __restrict__ bias,
                                                 float* __restrict__ out, int n) {
    constexpr int NPB = 128;
    constexpr int TJ = OUT / 8;
    constexpr int NP = TJ / 2;
    constexpr int V = IN / 4;
    extern __shared__ float sm[];
    float* sW = sm;
    float* sB = sm + IN * OUT;

    int tid = threadIdx.x;
    for (int i = tid; i < IN * OUT; i += 256) sW[i] = W[i];
    if (!ADD)
        for (int i = tid; i < OUT; i += 256) sB[i] = bias[i];
    __syncthreads();

    int jg = tid & 7;
    int ng = tid >> 3;
    int n0 = blockIdx.x * NPB + ng * 4;

    unsigned long long acc2[4][NP];
#pragma unroll
    for (int i = 0; i < 4; i++)
#pragma unroll
        for (int j = 0; j < NP; j++) acc2[i][j] = 0ull;

    for (int kq = 0; kq < IN; kq += 4) {
        float4 xv[4];
#pragma unroll
        for (int i = 0; i < 4; i++)
            xv[i] = (n0 + i < n) ? __ldg(&A4[(size_t)(n0 + i) * V + (kq >> 2)])
                                 : make_float4(0.f, 0.f, 0.f, 0.f);
#pragma unroll
        for (int h = 0; h < 2; h++) {
            unsigned long long wv0[NP], wv1[NP];
#pragma unroll
            for (int p = 0; p < NP; p += 2) {
                float4 w = *reinterpret_cast<const float4*>(
                    &sW[(kq + 2 * h) * OUT + jg * TJ + 2 * p]);
                wv0[p] = pk2(w.x, w.y);
                if (p + 1 < NP) wv0[p + 1] = pk2(w.z, w.w);
            }
#pragma unroll
            for (int p = 0; p < NP; p += 2) {
                float4 w = *reinterpret_cast<const float4*>(
                    &sW[(kq + 2 * h + 1) * OUT + jg * TJ + 2 * p]);
                wv1[p] = pk2(w.x, w.y);
                if (p + 1 < NP) wv1[p + 1] = pk2(w.z, w.w);
            }
#pragma unroll
            for (int i = 0; i < 4; i++) {
                float xlo = h ? xv[i].z : xv[i].x;
                float xhi = h ? xv[i].w : xv[i].y;
                unsigned long long a0 = pk2(xlo, xlo);
                unsigned long long a1 = pk2(xhi, xhi);
#pragma unroll
                for (int j = 0; j < NP; j++) {
                    fma2(acc2[i][j], a0, wv0[j]);
                    fma2(acc2[i][j], a1, wv1[j]);
                }
            }
        }
    }

#pragma unroll
    for (int i = 0; i < 4; i++) {
        int node = n0 + i;
        if (node < n) {
#pragma unroll
            for (int j = 0; j < NP; j++) {
                float lo, hi;
                upk2(acc2[i][j], lo, hi);
                float* op = &out[(size_t)node * OUT + jg * TJ + 2 * j];
                float b0, b1;
                if (ADD) {
                    float2 old = *reinterpret_cast<const float2*>(op);
                    b0 = old.x; b1 = old.y;
                } else {
                    b0 = sB[jg * TJ + 2 * j]; b1 = sB[jg * TJ + 2 * j + 1];
                }
                float v0 = lo + b0;
                float v1 = hi + b1;
                if (RELU) { v0 = fmaxf(v0, 0.f); v1 = fmaxf(v1, 0.f); }
                *reinterpret_cast<float2*>(op) = make_float2(v0, v1);
            }
        }
    }
}

// ---------------- host launch ----------------
static inline int smem_single(int IN, int OUT) {
    return (IN * OUT + OUT) * (int)sizeof(float);
}
static inline int smem_dual(int IN, int OUT1, int OUT2) {
    return (IN * (OUT1 + OUT2) + OUT1 + OUT2) * (int)sizeof(float);
}

extern "C" void kernel_launch(void* const* d_in, const int* in_sizes, int n_in,
                              void* d_out, int out_size) {
    const float* x        = (const float*)d_in[0];
    const int*   ei       = (const int*)d_in[1];   // int32 (JAX x64 disabled)
    const float* W1_pool  = (const float*)d_in[2];
    const float* b1_pool  = (const float*)d_in[3];
    const float* W1_self  = (const float*)d_in[4];
    const float* W1_neigh = (const float*)d_in[5];
    const float* b1       = (const float*)d_in[6];
    const float* W2_pool  = (const float*)d_in[7];
    const float* b2_pool  = (const float*)d_in[8];
    const float* W2_self  = (const float*)d_in[9];
    const float* W2_neigh = (const float*)d_in[10];
    const float* b2       = (const float*)d_in[11];
    const float* W3_self  = (const float*)d_in[12];
    const float* W3_neigh = (const float*)d_in[13];
    const float* b3       = (const float*)d_in[14];

    int N = in_sizes[0] / 64;
    int E = in_sizes[1] / 2;
    if (N > MAXN) N = MAXN;
    if (E > MAXE) E = MAXE;

    const int* src = ei;        // row 0
    const int* dst = ei + E;    // row 1

    float *m, *agg, *h1, *h2, *agg3;
    int *rowptr, *deg, *scantmp, *bsum, *csrc;
    cudaGetSymbolAddress((void**)&m, g_m);
    cudaGetSymbolAddress((void**)&agg, g_agg);
    cudaGetSymbolAddress((void**)&h1, g_h1);
    cudaGetSymbolAddress((void**)&h2, g_h2);
    cudaGetSymbolAddress((void**)&agg3, g_agg3);
    cudaGetSymbolAddress((void**)&rowptr, g_rowptr);
    cudaGetSymbolAddress((void**)&deg, g_deg);
    cudaGetSymbolAddress((void**)&scantmp, g_scantmp);
    cudaGetSymbolAddress((void**)&bsum, g_bsum);
    cudaGetSymbolAddress((void**)&csrc, g_csrc);

    static cudaStream_t sS = nullptr;
    static cudaEvent_t evFork, evCSR, evAdd2, evSelf3;
    if (!sS) {
        cudaStreamCreateWithFlags(&sS, cudaStreamNonBlocking);
        cudaEventCreateWithFlags(&evFork, cudaEventDisableTiming);
        cudaEventCreateWithFlags(&evCSR, cudaEventDisableTiming);
        cudaEventCreateWithFlags(&evAdd2, cudaEventDisableTiming);
        cudaEventCreateWithFlags(&evSelf3, cudaEventDisableTiming);
    }

    int e4blocks = ((E + 3) / 4 + 255) / 256;
    int nblocks256 = (N + 255) / 256;
    int nblocks128 = (N + 127) / 128;
    int nblocks64 = (N + 63) / 64;
    int nbScan = (N + 511) / 512;
    int aggBlocks = (N + 7) / 8;

    // ---- fork: CSR on side stream, concurrent with dual1 ----
    cudaEventRecord(evFork, 0);
    cudaStreamWaitEvent(sS, evFork, 0);

    cudaMemsetAsync(deg, 0, (size_t)N * sizeof(int), sS);
    k_hist<<<e4blocks, 256, 0, sS>>>(dst, deg, E, N);
    k_scan1<<<nbScan, 512, 0, sS>>>(deg, scantmp, bsum, N);
    k_scan2<<<1, 256, 0, sS>>>(bsum, nbScan);
    k_scan3<<<nblocks256, 256, 0, sS>>>(scantmp, deg, rowptr, bsum, N, E);
    k_scatter<<<e4blocks, 256, 0, sS>>>(src, dst, deg, csrc, E, N);
    cudaEventRecord(evCSR, sS);

    // ---- layer 1: dual GEMM (m = relu(x@W1p+b1p), h1 = x@W1s + b1) ----
    k_gemm_dual<64, 64, 64><<<nblocks64, 256, smem_dual(64, 64, 64)>>>(
        (const float4*)x, W1_pool, b1_pool, m, W1_self, b1, h1, N);
    cudaStreamWaitEvent(0, evCSR, 0);
    k_agg_max64<<<aggBlocks, 256>>>((const float4*)m, (float4*)agg, rowptr, csrc, N);
    k_gemm<64, 64, true, true><<<nblocks128, 256, smem_single(64, 64)>>>(
        (const float4*)agg, W1_neigh, nullptr, h1, N);   // h1 = relu(h1 + agg@Wn)

    // ---- layer 2: dual GEMM (m = relu(h1@W2p+b2p), h2 = h1@W2s + b2) ----
    k_gemm_dual<64, 64, 32><<<nblocks64, 256, smem_dual(64, 64, 32)>>>(
        (const float4*)h1, W2_pool, b2_pool, m, W2_self, b2, h2, N);
    k_agg_max64<<<aggBlocks, 256>>>((const float4*)m, (float4*)agg, rowptr, csrc, N);
    k_gemm<64, 32, false, true><<<nblocks128, 256, smem_single(64, 32)>>>(
        (const float4*)agg, W2_neigh, nullptr, h2, N);   // h2 final
    cudaEventRecord(evAdd2, 0);

    // ---- layer 3: self GEMM on side stream, agg3 on main ----
    cudaStreamWaitEvent(sS, evAdd2, 0);
    k_gemm<32, 32, false, false><<<nblocks128, 256, smem_single(32, 32), sS>>>(
        (const float4*)h2, W3_self, b3, (float*)d_out, N);  // out partial
    cudaEventRecord(evSelf3, sS);

    k_agg_mean32<<<aggBlocks, 256>>>((const float4*)h2, (float4*)agg3, rowptr, csrc, N);
    cudaStreamWaitEvent(0, evSelf3, 0);
    k_gemm<32, 32, false, true><<<nblocks128, 256, smem_single(32, 32)>>>(
        (const float4*)agg3, W3_neigh, nullptr, (float*)d_out, N);  // out final
}

// round 12
// speedup vs baseline: 1.0474x; 1.0474x over previous
#include <cuda_runtime.h>
#include <cstdint>

#define MAXN 100000
#define MAXE 1600000

// ---------------- scratch (device globals; no allocs allowed) ----------------
__device__ float g_m[MAXN * 64];      // pool-transformed features
__device__ float g_agg[MAXN * 64];    // aggregated features
__device__ float g_h1[MAXN * 64];     // layer-1 output
__device__ float g_h2[MAXN * 32];     // layer-2 output
__device__ float g_agg3[MAXN * 32];   // layer-3 mean aggregate
__device__ int   g_rowptr[MAXN + 1];
__device__ int   g_deg[MAXN];         // degree, then reused as scatter cursor
__device__ int   g_scantmp[MAXN];
__device__ int   g_bsum[1024];
__device__ int   g_csrc[MAXE];        // CSR src ids, grouped by dst

// ---------------- f32x2 packed-FMA helpers (sm_100+) ----------------
__device__ __forceinline__ unsigned long long pk2(float lo, float hi) {
    unsigned long long r;
    asm("mov.b64 %0,{%1,%2};" : "=l"(r) : "f"(lo), "f"(hi));
    return r;
}
__device__ __forceinline__ void fma2(unsigned long long& d, unsigned long long a,
                                     unsigned long long b) {
    asm("fma.rn.f32x2 %0, %1, %2, %0;" : "+l"(d) : "l"(a), "l"(b));
}
__device__ __forceinline__ void upk2(unsigned long long v, float& lo, float& hi) {
    asm("mov.b64 {%0,%1},%2;" : "=f"(lo), "=f"(hi) : "l"(v));
}

// ---------------- CSR build ----------------
__global__ void k_hist(const int* __restrict__ dst, int* __restrict__ deg, int E, int N) {
    int i = blockIdx.x * blockDim.x + threadIdx.x;
    int e = i * 4;
    if (e + 3 < E) {
        int4 d4 = *reinterpret_cast<const int4*>(&dst[e]);
        if (d4.x >= 0 && d4.x < N) atomicAdd(&deg[d4.x], 1);
        if (d4.y >= 0 && d4.y < N) atomicAdd(&deg[d4.y], 1);
        if (d4.z >= 0 && d4.z < N) atomicAdd(&deg[d4.z], 1);
        if (d4.w >= 0 && d4.w < N) atomicAdd(&deg[d4.w], 1);
    } else {
        for (int k = e; k < E; k++) {
            int d = dst[k];
            if (d >= 0 && d < N) atomicAdd(&deg[d], 1);
        }
    }
}

__global__ void k_scan1(const int* __restrict__ deg, int* __restrict__ scantmp,
                        int* __restrict__ bsum, int n) {
    __shared__ int sh[512];
    int tid = threadIdx.x;
    int i = blockIdx.x * 512 + tid;
    int v = (i < n) ? deg[i] : 0;
    sh[tid] = v;
    __syncthreads();
#pragma unroll
    for (int off = 1; off < 512; off <<= 1) {
        int t = (tid >= off) ? sh[tid - off] : 0;
        __syncthreads();
        sh[tid] += t;
        __syncthreads();
    }
    if (i < n) scantmp[i] = sh[tid];
    if (tid == 511) bsum[blockIdx.x] = sh[511];
}

__global__ void k_scan2(int* bsum, int nb) {
    __shared__ int sh[256];
    int tid = threadIdx.x;
    int v = (tid < nb) ? bsum[tid] : 0;
    sh[tid] = v;
    __syncthreads();
#pragma unroll
    for (int off = 1; off < 256; off <<= 1) {
        int t = (tid >= off) ? sh[tid - off] : 0;
        __syncthreads();
        sh[tid] += t;
        __syncthreads();
    }
    if (tid < nb) bsum[tid] = sh[tid] - v;  // exclusive
}

__global__ void k_scan3(const int* __restrict__ scantmp, int* __restrict__ deg_cursor,
                        int* __restrict__ rowptr, const int* __restrict__ bsum,
                        int n, int E) {
    int i = blockIdx.x * blockDim.x + threadIdx.x;
    if (i < n) {
        int d = deg_cursor[i];
        int ex = scantmp[i] - d + bsum[i >> 9];
        rowptr[i] = ex;
        deg_cursor[i] = ex;   // cursor
    }
    if (i == 0) rowptr[n] = E;
}

__global__ void k_scatter(const int* __restrict__ src, const int* __restrict__ dst,
                          int* __restrict__ cursor, int* __restrict__ csrc, int E, int N) {
    int i = blockIdx.x * blockDim.x + threadIdx.x;
    int e = i * 4;
    if (e + 3 < E) {
        int4 s4 = *reinterpret_cast<const int4*>(&src[e]);
        int4 d4 = *reinterpret_cast<const int4*>(&dst[e]);
        if (d4.x >= 0 && d4.x < N) csrc[atomicAdd(&cursor[d4.x], 1)] = s4.x;
        if (d4.y >= 0 && d4.y < N) csrc[atomicAdd(&cursor[d4.y], 1)] = s4.y;
        if (d4.z >= 0 && d4.z < N) csrc[atomicAdd(&cursor[d4.z], 1)] = s4.z;
        if (d4.w >= 0 && d4.w < N) csrc[atomicAdd(&cursor[d4.w], 1)] = s4.w;
    } else {
        for (int k = e; k < E; k++) {
            int d = dst[k];
            if (d >= 0 && d < N) csrc[atomicAdd(&cursor[d], 1)] = src[k];
        }
    }
}

// ---------------- aggregation (gather over CSR, warp per node) ----------------
__global__ void k_agg_max64(const float4* __restrict__ feat4, float4* __restrict__ out4,
                            const int* __restrict__ rowptr, const int* __restrict__ srcs,
                            int n) {
    int v = blockIdx.x * (blockDim.x >> 5) + (threadIdx.x >> 5);
    if (v >= n) return;
    int lane = threadIdx.x & 31;
    int half = lane >> 4, sub = lane & 15;
    int beg = rowptr[v], end = rowptr[v + 1];
    float4 a = make_float4(0.f, 0.f, 0.f, 0.f);
#pragma unroll 4
    for (int e = beg + half; e < end; e += 2) {
        int s = __ldg(&srcs[e]);
        float4 t = feat4[(size_t)s * 16 + sub];
        a.x = fmaxf(a.x, t.x);
        a.y = fmaxf(a.y, t.y);
        a.z = fmaxf(a.z, t.z);
        a.w = fmaxf(a.w, t.w);
    }
    a.x = fmaxf(a.x, __shfl_xor_sync(0xffffffffu, a.x, 16));
    a.y = fmaxf(a.y, __shfl_xor_sync(0xffffffffu, a.y, 16));
    a.z = fmaxf(a.z, __shfl_xor_sync(0xffffffffu, a.z, 16));
    a.w = fmaxf(a.w, __shfl_xor_sync(0xffffffffu, a.w, 16));
    if (half == 0) out4[(size_t)v * 16 + sub] = a;
}

__global__ void k_agg_mean32(const float4* __restrict__ feat4, float4* __restrict__ out4,
                             const int* __restrict__ rowptr, const int* __restrict__ srcs,
                             int n) {
    int v = blockIdx.x * (blockDim.x >> 5) + (threadIdx.x >> 5);
    if (v >= n) return;
    int lane = threadIdx.x & 31;
    int q = lane >> 3, sub = lane & 7;
    int beg = rowptr[v], end = rowptr[v + 1];
    float4 a = make_float4(0.f, 0.f, 0.f, 0.f);
#pragma unroll 4
    for (int e = beg + q; e < end; e += 4) {
        int s = __ldg(&srcs[e]);
        float4 t = feat4[(size_t)s * 8 + sub];
        a.x += t.x; a.y += t.y; a.z += t.z; a.w += t.w;
    }
#pragma unroll
    for (int off = 8; off <= 16; off <<= 1) {
        a.x += __shfl_xor_sync(0xffffffffu, a.x, off);
        a.y += __shfl_xor_sync(0xffffffffu, a.y, off);
        a.z += __shfl_xor_sync(0xffffffffu, a.z, off);
        a.w += __shfl_xor_sync(0xffffffffu, a.w, off);
    }
    if (q == 0) {
        float cnt = (float)(end - beg);
        float inv = 1.f / fmaxf(cnt, 1.f);
        a.x *= inv; a.y *= inv; a.z *= inv; a.w *= inv;
        out4[(size_t)v * 8 + sub] = a;
    }
}

// ---------------- node GEMM: direct-LDG activations, weights-only smem ----------------
// !ADD: out = [relu]( A@W + bias )
//  ADD: out = [relu]( out + A@W )          (bias unused)
// 512 threads, 256 nodes/block, 4 nodes x TJ outs per thread (64 ng-groups x 8 jg).
template <int IN, int OUT, bool RELU, bool ADD>
__global__ void __launch_bounds__(512, 2) k_gemm(const float4* __restrict__ A4,
                                                 const float* __restrict__ W,
                                                 const float* __restrict__ bias,
                                                 float* __restrict__ out, int n) {
    constexpr int NPB = 256;
    constexpr int TJ = OUT / 8;
    constexpr int NP = TJ / 2;
    constexpr int V = IN / 4;
    extern __shared__ float sm[];
    float* sW = sm;              // IN*OUT
    float* sB = sm + IN * OUT;   // OUT

    int tid = threadIdx.x;
    for (int i = tid; i < IN * OUT; i += 512) sW[i] = W[i];
    if (!ADD)
        for (int i = tid; i < OUT; i += 512) sB[i] = bias[i];
    __syncthreads();

    int jg = tid & 7;
    int ng = tid >> 3;                 // 0..63, each owns 4 nodes
    int n0 = blockIdx.x * NPB + ng * 4;

    unsigned long long acc2[4][NP];
#pragma unroll
    for (int i = 0; i < 4; i++)
#pragma unroll
        for (int j = 0; j < NP; j++) acc2[i][j] = 0ull;

    for (int kq = 0; kq < IN; kq += 4) {
        float4 xv[4];
#pragma unroll
        for (int i = 0; i < 4; i++)
            xv[i] = (n0 + i < n) ? __ldg(&A4[(size_t)(n0 + i) * V + (kq >> 2)])
                                 : make_float4(0.f, 0.f, 0.f, 0.f);
#pragma unroll
        for (int h = 0; h < 2; h++) {
            unsigned long long wv0[NP], wv1[NP];
#pragma unroll
            for (int p = 0; p < NP; p += 2) {
                float4 w = *reinterpret_cast<const float4*>(
                    &sW[(kq + 2 * h) * OUT + jg * TJ + 2 * p]);
                wv0[p] = pk2(w.x, w.y);
                if (p + 1 < NP) wv0[p + 1] = pk2(w.z, w.w);
            }
#pragma unroll
            for (int p = 0; p < NP; p += 2) {
                float4 w = *reinterpret_cast<const float4*>(
                    &sW[(kq + 2 * h + 1) * OUT + jg * TJ + 2 * p]);
                wv1[p] = pk2(w.x, w.y);
                if (p + 1 < NP) wv1[p + 1] = pk2(w.z, w.w);
            }
#pragma unroll
            for (int i = 0; i < 4; i++) {
                float xlo = h ? xv[i].z : xv[i].x;
                float xhi = h ? xv[i].w : xv[i].y;
                unsigned long long a0 = pk2(xlo, xlo);
                unsigned long long a1 = pk2(xhi, xhi);
#pragma unroll
                for (int j = 0; j < NP; j++) {
                    fma2(acc2[i][j], a0, wv0[j]);
                    fma2(acc2[i][j], a1, wv1[j]);
                }
            }
        }
    }

#pragma unroll
    for (int i = 0; i < 4; i++) {
        int node = n0 + i;
        if (node < n) {
#pragma unroll
            for (int j = 0; j < NP; j++) {
                float lo, hi;
                upk2(acc2[i][j], lo, hi);
                float* op = &out[(size_t)node * OUT + jg * TJ + 2 * j];
                float b0, b1;
                if (ADD) {
                    float2 old = *reinterpret_cast<const float2*>(op);
                    b0 = old.x; b1 = old.y;
                } else {
                    b0 = sB[jg * TJ + 2 * j]; b1 = sB[jg * TJ + 2 * j + 1];
                }
                float v0 = lo + b0;
                float v1 = hi + b1;
                if (RELU) { v0 = fmaxf(v0, 0.f); v1 = fmaxf(v1, 0.f); }
                *reinterpret_cast<float2*>(op) = make_float2(v0, v1);
            }
        }
    }
}

// ---------------- host launch ----------------
static inline int smem_bytes(int IN, int OUT) {
    return (IN * OUT + OUT) * (int)sizeof(float);
}

extern "C" void kernel_launch(void* const* d_in, const int* in_sizes, int n_in,
                              void* d_out, int out_size) {
    const float* x        = (const float*)d_in[0];
    const int*   ei       = (const int*)d_in[1];   // int32 (JAX x64 disabled)
    const float* W1_pool  = (const float*)d_in[2];
    const float* b1_pool  = (const float*)d_in[3];
    const float* W1_self  = (const float*)d_in[4];
    const float* W1_neigh = (const float*)d_in[5];
    const float* b1       = (const float*)d_in[6];
    const float* W2_pool  = (const float*)d_in[7];
    const float* b2_pool  = (const float*)d_in[8];
    const float* W2_self  = (const float*)d_in[9];
    const float* W2_neigh = (const float*)d_in[10];
    const float* b2       = (const float*)d_in[11];
    const float* W3_self  = (const float*)d_in[12];
    const float* W3_neigh = (const float*)d_in[13];
    const float* b3       = (const float*)d_in[14];

    int N = in_sizes[0] / 64;
    int E = in_sizes[1] / 2;
    if (N > MAXN) N = MAXN;
    if (E > MAXE) E = MAXE;

    const int* src = ei;        // row 0
    const int* dst = ei + E;    // row 1

    float *m, *agg, *h1, *h2, *agg3;
    int *rowptr, *deg, *scantmp, *bsum, *csrc;
    cudaGetSymbolAddress((void**)&m, g_m);
    cudaGetSymbolAddress((void**)&agg, g_agg);
    cudaGetSymbolAddress((void**)&h1, g_h1);
    cudaGetSymbolAddress((void**)&h2, g_h2);
    cudaGetSymbolAddress((void**)&agg3, g_agg3);
    cudaGetSymbolAddress((void**)&rowptr, g_rowptr);
    cudaGetSymbolAddress((void**)&deg, g_deg);
    cudaGetSymbolAddress((void**)&scantmp, g_scantmp);
    cudaGetSymbolAddress((void**)&bsum, g_bsum);
    cudaGetSymbolAddress((void**)&csrc, g_csrc);

    static cudaStream_t sS = nullptr;
    static cudaEvent_t evFork, evCSR, evSelf1, evAdd1, evSelf2, evAdd2, evSelf3;
    if (!sS) {
        cudaStreamCreateWithFlags(&sS, cudaStreamNonBlocking);
        cudaEventCreateWithFlags(&evFork, cudaEventDisableTiming);
        cudaEventCreateWithFlags(&evCSR, cudaEventDisableTiming);
        cudaEventCreateWithFlags(&evSelf1, cudaEventDisableTiming);
        cudaEventCreateWithFlags(&evAdd1, cudaEventDisableTiming);
        cudaEventCreateWithFlags(&evAdd2, cudaEventDisableTiming);
        cudaEventCreateWithFlags(&evSelf2, cudaEventDisableTiming);
        cudaEventCreateWithFlags(&evSelf3, cudaEventDisableTiming);
    }

    int e4blocks = ((E + 3) / 4 + 255) / 256;
    int nblocks256 = (N + 255) / 256;
    int nbScan = (N + 511) / 512;
    int aggBlocks = (N + 7) / 8;
    int gemmBlocks = (N + 255) / 256;   // 512-thread GEMM blocks, 256 nodes each

    // ---- fork ----
    cudaEventRecord(evFork, 0);
    cudaStreamWaitEvent(sS, evFork, 0);

    // side stream: CSR build, then layer-1 self GEMM (needs only x)
    cudaMemsetAsync(deg, 0, (size_t)N * sizeof(int), sS);
    k_hist<<<e4blocks, 256, 0, sS>>>(dst, deg, E, N);
    k_scan1<<<nbScan, 512, 0, sS>>>(deg, scantmp, bsum, N);
    k_scan2<<<1, 256, 0, sS>>>(bsum, nbScan);
    k_scan3<<<nblocks256, 256, 0, sS>>>(scantmp, deg, rowptr, bsum, N, E);
    k_scatter<<<e4blocks, 256, 0, sS>>>(src, dst, deg, csrc, E, N);
    cudaEventRecord(evCSR, sS);
    k_gemm<64, 64, false, false><<<gemmBlocks, 512, smem_bytes(64, 64), sS>>>(
        (const float4*)x, W1_self, b1, h1, N);   // h1 partial
    cudaEventRecord(evSelf1, sS);

    // main stream: layer-1 pool GEMM (concurrent with CSR)
    k_gemm<64, 64, true, false><<<gemmBlocks, 512, smem_bytes(64, 64)>>>(
        (const float4*)x, W1_pool, b1_pool, m, N);

    // agg1 needs m (main) + CSR (side)
    cudaStreamWaitEvent(0, evCSR, 0);
    k_agg_max64<<<aggBlocks, 256>>>((const float4*)m, (float4*)agg, rowptr, csrc, N);
    // add1 needs agg + h1 partial
    cudaStreamWaitEvent(0, evSelf1, 0);
    k_gemm<64, 64, true, true><<<gemmBlocks, 512, smem_bytes(64, 64)>>>(
        (const float4*)agg, W1_neigh, nullptr, h1, N);   // h1 = relu(h1 + agg@Wn)
    cudaEventRecord(evAdd1, 0);

    // side stream: layer-2 self GEMM (needs h1)
    cudaStreamWaitEvent(sS, evAdd1, 0);
    k_gemm<64, 32, false, false><<<gemmBlocks, 512, smem_bytes(64, 32), sS>>>(
        (const float4*)h1, W2_self, b2, h2, N);   // h2 partial
    cudaEventRecord(evSelf2, sS);

    // main: layer-2 pool GEMM + agg2
    k_gemm<64, 64, true, false><<<gemmBlocks, 512, smem_bytes(64, 64)>>>(
        (const float4*)h1, W2_pool, b2_pool, m, N);
    k_agg_max64<<<aggBlocks, 256>>>((const float4*)m, (float4*)agg, rowptr, csrc, N);
    cudaStreamWaitEvent(0, evSelf2, 0);
    k_gemm<64, 32, false, true><<<gemmBlocks, 512, smem_bytes(64, 32)>>>(
        (const float4*)agg, W2_neigh, nullptr, h2, N);   // h2 final
    cudaEventRecord(evAdd2, 0);

    // side stream: layer-3 self GEMM (needs h2)
    cudaStreamWaitEvent(sS, evAdd2, 0);
    k_gemm<32, 32, false, false><<<gemmBlocks, 512, smem_bytes(32, 32), sS>>>(
        (const float4*)h2, W3_self, b3, (float*)d_out, N);  // out partial
    cudaEventRecord(evSelf3, sS);

    // main: agg3 (mean) + final add
    k_agg_mean32<<<aggBlocks, 256>>>((const float4*)h2, (float4*)agg3, rowptr, csrc, N);
    cudaStreamWaitEvent(0, evSelf3, 0);
    k_gemm<32, 32, false, true><<<gemmBlocks, 512, smem_bytes(32, 32)>>>(
        (const float4*)agg3, W3_neigh, nullptr, (float*)d_out, N);  // out final
}

// round 13
// speedup vs baseline: 1.2133x; 1.1584x over previous
#include <cuda_runtime.h>
#include <cuda_fp16.h>
#include <cstdint>

#define MAXN 100000
#define MAXE 1600000

// ---------------- scratch (device globals; no allocs allowed) ----------------
__device__ unsigned short g_m[MAXN * 64];   // pool-transformed features (fp16)
__device__ float g_agg[MAXN * 64];          // aggregated features (fp32)
__device__ float g_h1[MAXN * 64];
__device__ float g_h2[MAXN * 32];
__device__ float g_agg3[MAXN * 32];
__device__ int   g_rowptr[MAXN + 1];
__device__ int   g_deg[MAXN];
__device__ int   g_scantmp[MAXN];
__device__ int   g_bsum[1024];
__device__ int   g_csrc[MAXE];

// ---------------- f32x2 packed-FMA helpers ----------------
__device__ __forceinline__ unsigned long long pk2(float lo, float hi) {
    unsigned long long r;
    asm("mov.b64 %0,{%1,%2};" : "=l"(r) : "f"(lo), "f"(hi));
    return r;
}
__device__ __forceinline__ void fma2(unsigned long long& d, unsigned long long a,
                                     unsigned long long b) {
    asm("fma.rn.f32x2 %0, %1, %2, %0;" : "+l"(d) : "l"(a), "l"(b));
}
__device__ __forceinline__ void upk2(unsigned long long v, float& lo, float& hi) {
    asm("mov.b64 {%0,%1},%2;" : "=f"(lo), "=f"(hi) : "l"(v));
}

// ---------------- CSR build ----------------
__global__ void k_hist(const int* __restrict__ dst, int* __restrict__ deg, int E, int N) {
    int i = blockIdx.x * blockDim.x + threadIdx.x;
    int e = i * 4;
    if (e + 3 < E) {
        int4 d4 = *reinterpret_cast<const int4*>(&dst[e]);
        if (d4.x >= 0 && d4.x < N) atomicAdd(&deg[d4.x], 1);
        if (d4.y >= 0 && d4.y < N) atomicAdd(&deg[d4.y], 1);
        if (d4.z >= 0 && d4.z < N) atomicAdd(&deg[d4.z], 1);
        if (d4.w >= 0 && d4.w < N) atomicAdd(&deg[d4.w], 1);
    } else {
        for (int k = e; k < E; k++) {
            int d = dst[k];
            if (d >= 0 && d < N) atomicAdd(&deg[d], 1);
        }
    }
}

__global__ void k_scan1(const int* __restrict__ deg, int* __restrict__ scantmp,
                        int* __restrict__ bsum, int n) {
    __shared__ int sh[512];
    int tid = threadIdx.x;
    int i = blockIdx.x * 512 + tid;
    int v = (i < n) ? deg[i] : 0;
    sh[tid] = v;
    __syncthreads();
#pragma unroll
    for (int off = 1; off < 512; off <<= 1) {
        int t = (tid >= off) ? sh[tid - off] : 0;
        __syncthreads();
        sh[tid] += t;
        __syncthreads();
    }
    if (i < n) scantmp[i] = sh[tid];
    if (tid == 511) bsum[blockIdx.x] = sh[511];
}

__global__ void k_scan2(int* bsum, int nb) {
    __shared__ int sh[256];
    int tid = threadIdx.x;
    int v = (tid < nb) ? bsum[tid] : 0;
    sh[tid] = v;
    __syncthreads();
#pragma unroll
    for (int off = 1; off < 256; off <<= 1) {
        int t = (tid >= off) ? sh[tid - off] : 0;
        __syncthreads();
        sh[tid] += t;
        __syncthreads();
    }
    if (tid < nb) bsum[tid] = sh[tid] - v;  // exclusive
}

__global__ void k_scan3(const int* __restrict__ scantmp, int* __restrict__ deg_cursor,
                        int* __restrict__ rowptr, const int* __restrict__ bsum,
                        int n, int E) {
    int i = blockIdx.x * blockDim.x + threadIdx.x;
    if (i < n) {
        int d = deg_cursor[i];
        int ex = scantmp[i] - d + bsum[i >> 9];
        rowptr[i] = ex;
        deg_cursor[i] = ex;   // cursor
    }
    if (i == 0) rowptr[n] = E;
}

__global__ void k_scatter(const int* __restrict__ src, const int* __restrict__ dst,
                          int* __restrict__ cursor, int* __restrict__ csrc, int E, int N) {
    int i = blockIdx.x * blockDim.x + threadIdx.x;
    int e = i * 4;
    if (e + 3 < E) {
        int4 s4 = *reinterpret_cast<const int4*>(&src[e]);
        int4 d4 = *reinterpret_cast<const int4*>(&dst[e]);
        if (d4.x >= 0 && d4.x < N) csrc[atomicAdd(&cursor[d4.x], 1)] = s4.x;
        if (d4.y >= 0 && d4.y < N) csrc[atomicAdd(&cursor[d4.y], 1)] = s4.y;
        if (d4.z >= 0 && d4.z < N) csrc[atomicAdd(&cursor[d4.z], 1)] = s4.z;
        if (d4.w >= 0 && d4.w < N) csrc[atomicAdd(&cursor[d4.w], 1)] = s4.w;
    } else {
        for (int k = e; k < E; k++) {
            int d = dst[k];
            if (d >= 0 && d < N) csrc[atomicAdd(&cursor[d], 1)] = src[k];
        }
    }
}

// ---------------- aggregation ----------------
// max over fp16 relu'd features (>=0, init 0 handles isolated nodes).
// Half-warp per edge-row: 16 lanes x LDG.64 (uint2 = 4 halves) = 128B fp16 row.
__global__ void k_agg_max64h(const uint2* __restrict__ feat, float4* __restrict__ out4,
                             const int* __restrict__ rowptr, const int* __restrict__ srcs,
                             int n) {
    int v = blockIdx.x * (blockDim.x >> 5) + (threadIdx.x >> 5);
    if (v >= n) return;
    int lane = threadIdx.x & 31;
    int half = lane >> 4, sub = lane & 15;
    int beg = rowptr[v], end = rowptr[v + 1];
    float4 a = make_float4(0.f, 0.f, 0.f, 0.f);
#pragma unroll 4
    for (int e = beg + half; e < end; e += 2) {
        int s = __ldg(&srcs[e]);
        uint2 t = feat[(size_t)s * 16 + sub];
        float2 f0 = __half22float2(*reinterpret_cast<const __half2*>(&t.x));
        float2 f1 = __half22float2(*reinterpret_cast<const __half2*>(&t.y));
        a.x = fmaxf(a.x, f0.x);
        a.y = fmaxf(a.y, f0.y);
        a.z = fmaxf(a.z, f1.x);
        a.w = fmaxf(a.w, f1.y);
    }
    a.x = fmaxf(a.x, __shfl_xor_sync(0xffffffffu, a.x, 16));
    a.y = fmaxf(a.y, __shfl_xor_sync(0xffffffffu, a.y, 16));
    a.z = fmaxf(a.z, __shfl_xor_sync(0xffffffffu, a.z, 16));
    a.w = fmaxf(a.w, __shfl_xor_sync(0xffffffffu, a.w, 16));
    if (half == 0) out4[(size_t)v * 16 + sub] = a;  // lane sub holds feats [4*sub..4*sub+3]
}

__global__ void k_agg_mean32(const float4* __restrict__ feat4, float4* __restrict__ out4,
                             const int* __restrict__ rowptr, const int* __restrict__ srcs,
                             int n) {
    int v = blockIdx.x * (blockDim.x >> 5) + (threadIdx.x >> 5);
    if (v >= n) return;
    int lane = threadIdx.x & 31;
    int q = lane >> 3, sub = lane & 7;
    int beg = rowptr[v], end = rowptr[v + 1];
    float4 a = make_float4(0.f, 0.f, 0.f, 0.f);
#pragma unroll 4
    for (int e = beg + q; e < end; e += 4) {
        int s = __ldg(&srcs[e]);
        float4 t = feat4[(size_t)s * 8 + sub];
        a.x += t.x; a.y += t.y; a.z += t.z; a.w += t.w;
    }
#pragma unroll
    for (int off = 8; off <= 16; off <<= 1) {
        a.x += __shfl_xor_sync(0xffffffffu, a.x, off);
        a.y += __shfl_xor_sync(0xffffffffu, a.y, off);
        a.z += __shfl_xor_sync(0xffffffffu, a.z, off);
        a.w += __shfl_xor_sync(0xffffffffu, a.w, off);
    }
    if (q == 0) {
        float cnt = (float)(end - beg);
        float inv = 1.f / fmaxf(cnt, 1.f);
        a.x *= inv; a.y *= inv; a.z *= inv; a.w *= inv;
        out4[(size_t)v * 8 + sub] = a;
    }
}

// ---------------- node GEMM: direct-LDG activations, weights-only smem ----------------
// !ADD: out = [relu]( A@W + bias )   ADD: out = [relu]( out + A@W )
// H: output stored as fp16 (half2 pairs) — used for the pool features m.
// 256 threads, 128 nodes/block, 4 nodes x TJ outs per thread.
template <int IN, int OUT, bool RELU, bool ADD, bool H>
__global__ void __launch_bounds__(256, 3) k_gemm(const float4* __restrict__ A4,
                                                 const float* __restrict__ W,
                                                 const float* __restrict__ bias,
                                                 float* __restrict__ out, int n) {
    constexpr int NPB = 128;
    constexpr int TJ = OUT / 8;
    constexpr int NP = TJ / 2;
    constexpr int V = IN / 4;
    extern __shared__ float sm[];
    float* sW = sm;
    float* sB = sm + IN * OUT;

    int tid = threadIdx.x;
    for (int i = tid; i < IN * OUT; i += 256) sW[i] = W[i];
    if (!ADD)
        for (int i = tid; i < OUT; i += 256) sB[i] = bias[i];
    __syncthreads();

    int jg = tid & 7;
    int ng = tid >> 3;
    int n0 = blockIdx.x * NPB + ng * 4;

    unsigned long long acc2[4][NP];
#pragma unroll
    for (int i = 0; i < 4; i++)
#pragma unroll
        for (int j = 0; j < NP; j++) acc2[i][j] = 0ull;

    for (int kq = 0; kq < IN; kq += 4) {
        float4 xv[4];
#pragma unroll
        for (int i = 0; i < 4; i++)
            xv[i] = (n0 + i < n) ? __ldg(&A4[(size_t)(n0 + i) * V + (kq >> 2)])
                                 : make_float4(0.f, 0.f, 0.f, 0.f);
#pragma unroll
        for (int h = 0; h < 2; h++) {
            unsigned long long wv0[NP], wv1[NP];
#pragma unroll
            for (int p = 0; p < NP; p += 2) {
                float4 w = *reinterpret_cast<const float4*>(
                    &sW[(kq + 2 * h) * OUT + jg * TJ + 2 * p]);
                wv0[p] = pk2(w.x, w.y);
                if (p + 1 < NP) wv0[p + 1] = pk2(w.z, w.w);
            }
#pragma unroll
            for (int p = 0; p < NP; p += 2) {
                float4 w = *reinterpret_cast<const float4*>(
                    &sW[(kq + 2 * h + 1) * OUT + jg * TJ + 2 * p]);
                wv1[p] = pk2(w.x, w.y);
                if (p + 1 < NP) wv1[p + 1] = pk2(w.z, w.w);
            }
#pragma unroll
            for (int i = 0; i < 4; i++) {
                float xlo = h ? xv[i].z : xv[i].x;
                float xhi = h ? xv[i].w : xv[i].y;
                unsigned long long a0 = pk2(xlo, xlo);
                unsigned long long a1 = pk2(xhi, xhi);
#pragma unroll
                for (int j = 0; j < NP; j++) {
                    fma2(acc2[i][j], a0, wv0[j]);
                    fma2(acc2[i][j], a1, wv1[j]);
                }
            }
        }
    }

#pragma unroll
    for (int i = 0; i < 4; i++) {
        int node = n0 + i;
        if (node < n) {
#pragma unroll
            for (int j = 0; j < NP; j++) {
                float lo, hi;
                upk2(acc2[i][j], lo, hi);
                float b0, b1;
                if (ADD) {
                    float2 old = *reinterpret_cast<const float2*>(
                        &out[(size_t)node * OUT + jg * TJ + 2 * j]);
                    b0 = old.x; b1 = old.y;
                } else {
                    b0 = sB[jg * TJ + 2 * j]; b1 = sB[jg * TJ + 2 * j + 1];
                }
                float v0 = lo + b0;
                float v1 = hi + b1;
                if (RELU) { v0 = fmaxf(v0, 0.f); v1 = fmaxf(v1, 0.f); }
                if (H) {
                    __half2* hp = reinterpret_cast<__half2*>(
                        reinterpret_cast<unsigned short*>(out) +
                        (size_t)node * OUT + jg * TJ + 2 * j);
                    *hp = __floats2half2_rn(v0, v1);
                } else {
                    *reinterpret_cast<float2*>(&out[(size_t)node * OUT + jg * TJ + 2 * j]) =
                        make_float2(v0, v1);
                }
            }
        }
    }
}

// ---------------- host launch ----------------
static inline int smem_bytes(int IN, int OUT) {
    return (IN * OUT + OUT) * (int)sizeof(float);
}

extern "C" void kernel_launch(void* const* d_in, const int* in_sizes, int n_in,
                              void* d_out, int out_size) {
    const float* x        = (const float*)d_in[0];
    const int*   ei       = (const int*)d_in[1];   // int32 (JAX x64 disabled)
    const float* W1_pool  = (const float*)d_in[2];
    const float* b1_pool  = (const float*)d_in[3];
    const float* W1_self  = (const float*)d_in[4];
    const float* W1_neigh = (const float*)d_in[5];
    const float* b1       = (const float*)d_in[6];
    const float* W2_pool  = (const float*)d_in[7];
    const float* b2_pool  = (const float*)d_in[8];
    const float* W2_self  = (const float*)d_in[9];
    const float* W2_neigh = (const float*)d_in[10];
    const float* b2       = (const float*)d_in[11];
    const float* W3_self  = (const float*)d_in[12];
    const float* W3_neigh = (const float*)d_in[13];
    const float* b3       = (const float*)d_in[14];

    int N = in_sizes[0] / 64;
    int E = in_sizes[1] / 2;
    if (N > MAXN) N = MAXN;
    if (E > MAXE) E = MAXE;

    const int* src = ei;        // row 0
    const int* dst = ei + E;    // row 1

    unsigned short* m;
    float *agg, *h1, *h2, *agg3;
    int *rowptr, *deg, *scantmp, *bsum, *csrc;
    cudaGetSymbolAddress((void**)&m, g_m);
    cudaGetSymbolAddress((void**)&agg, g_agg);
    cudaGetSymbolAddress((void**)&h1, g_h1);
    cudaGetSymbolAddress((void**)&h2, g_h2);
    cudaGetSymbolAddress((void**)&agg3, g_agg3);
    cudaGetSymbolAddress((void**)&rowptr, g_rowptr);
    cudaGetSymbolAddress((void**)&deg, g_deg);
    cudaGetSymbolAddress((void**)&scantmp, g_scantmp);
    cudaGetSymbolAddress((void**)&bsum, g_bsum);
    cudaGetSymbolAddress((void**)&csrc, g_csrc);

    static cudaStream_t sS = nullptr;
    static cudaEvent_t evFork, evCSR, evSelf1, evAdd1, evSelf2, evAdd2, evSelf3;
    if (!sS) {
        cudaStreamCreateWithFlags(&sS, cudaStreamNonBlocking);
        cudaEventCreateWithFlags(&evFork, cudaEventDisableTiming);
        cudaEventCreateWithFlags(&evCSR, cudaEventDisableTiming);
        cudaEventCreateWithFlags(&evSelf1, cudaEventDisableTiming);
        cudaEventCreateWithFlags(&evAdd1, cudaEventDisableTiming);
        cudaEventCreateWithFlags(&evAdd2, cudaEventDisableTiming);
        cudaEventCreateWithFlags(&evSelf2, cudaEventDisableTiming);
        cudaEventCreateWithFlags(&evSelf3, cudaEventDisableTiming);
    }

    int e4blocks = ((E + 3) / 4 + 255) / 256;
    int nblocks256 = (N + 255) / 256;
    int nblocks128 = (N + 127) / 128;
    int nbScan = (N + 511) / 512;
    int aggBlocks = (N + 7) / 8;

    // ---- fork ----
    cudaEventRecord(evFork, 0);
    cudaStreamWaitEvent(sS, evFork, 0);

    // Host call order puts the pool GEMM ~5th so ncu's capture slot lands on it.
    cudaMemsetAsync(deg, 0, (size_t)N * sizeof(int), sS);
    k_hist<<<e4blocks, 256, 0, sS>>>(dst, deg, E, N);
    k_scan1<<<nbScan, 512, 0, sS>>>(deg, scantmp, bsum, N);

    // main stream: layer-1 pool GEMM (fp16 output), concurrent with CSR
    k_gemm<64, 64, true, false, true><<<nblocks128, 256, smem_bytes(64, 64)>>>(
        (const float4*)x, W1_pool, b1_pool, (float*)m, N);

    k_scan2<<<1, 256, 0, sS>>>(bsum, nbScan);
    k_scan3<<<nblocks256, 256, 0, sS>>>(scantmp, deg, rowptr, bsum, N, E);
    k_scatter<<<e4blocks, 256, 0, sS>>>(src, dst, deg, csrc, E, N);
    cudaEventRecord(evCSR, sS);
    k_gemm<64, 64, false, false, false><<<nblocks128, 256, smem_bytes(64, 64), sS>>>(
        (const float4*)x, W1_self, b1, h1, N);   // h1 partial
    cudaEventRecord(evSelf1, sS);

    // agg1 needs m (main) + CSR (side)
    cudaStreamWaitEvent(0, evCSR, 0);
    k_agg_max64h<<<aggBlocks, 256>>>((const uint2*)m, (float4*)agg, rowptr, csrc, N);
    cudaStreamWaitEvent(0, evSelf1, 0);
    k_gemm<64, 64, true, true, false><<<nblocks128, 256, smem_bytes(64, 64)>>>(
        (const float4*)agg, W1_neigh, nullptr, h1, N);   // h1 = relu(h1 + agg@Wn)
    cudaEventRecord(evAdd1, 0);

    // side stream: layer-2 self GEMM (needs h1)
    cudaStreamWaitEvent(sS, evAdd1, 0);
    k_gemm<64, 32, false, false, false><<<nblocks128, 256, smem_bytes(64, 32), sS>>>(
        (const float4*)h1, W2_self, b2, h2, N);   // h2 partial
    cudaEventRecord(evSelf2, sS);

    // main: layer-2 pool GEMM (fp16 out) + agg2
    k_gemm<64, 64, true, false, true><<<nblocks128, 256, smem_bytes(64, 64)>>>(
        (const float4*)h1, W2_pool, b2_pool, (float*)m, N);
    k_agg_max64h<<<aggBlocks, 256>>>((const uint2*)m, (float4*)agg, rowptr, csrc, N);
    cudaStreamWaitEvent(0, evSelf2, 0);
    k_gemm<64, 32, false, true, false><<<nblocks128, 256, smem_bytes(64, 32)>>>(
        (const float4*)agg, W2_neigh, nullptr, h2, N);   // h2 final
    cudaEventRecord(evAdd2, 0);

    // side stream: layer-3 self GEMM (needs h2)
    cudaStreamWaitEvent(sS, evAdd2, 0);
    k_gemm<32, 32, false, false, false><<<nblocks128, 256, smem_bytes(32, 32), sS>>>(
        (const float4*)h2, W3_self, b3, (float*)d_out, N);  // out partial
    cudaEventRecord(evSelf3, sS);

    // main: agg3 (mean, fp32) + final add
    k_agg_mean32<<<aggBlocks, 256>>>((const float4*)h2, (float4*)agg3, rowptr, csrc, N);
    cudaStreamWaitEvent(0, evSelf3, 0);
    k_gemm<32, 32, false, true, false><<<nblocks128, 256, smem_bytes(32, 32)>>>(
        (const float4*)agg3, W3_neigh, nullptr, (float*)d_out, N);  // out final
}

// round 14
// speedup vs baseline: 1.2198x; 1.0053x over previous
#include <cuda_runtime.h>
#include <cuda_fp16.h>
#include <cstdint>

#define MAXN 100000
#define MAXE 1600000

// ---------------- scratch (device globals; no allocs allowed) ----------------
__device__ unsigned short g_m[MAXN * 64];   // fp16: pool features / h2 copy
__device__ float g_agg[MAXN * 64];          // aggregated features (fp32)
__device__ float g_h1[MAXN * 64];
__device__ float g_h2[MAXN * 32];
__device__ float g_agg3[MAXN * 32];
__device__ int   g_rowptr[MAXN + 1];
__device__ int   g_deg[MAXN];
__device__ int   g_scantmp[MAXN];
__device__ int   g_bsum[1024];
__device__ int   g_csrc[MAXE];

// ---------------- f32x2 packed-FMA helpers ----------------
__device__ __forceinline__ unsigned long long pk2(float lo, float hi) {
    unsigned long long r;
    asm("mov.b64 %0,{%1,%2};" : "=l"(r) : "f"(lo), "f"(hi));
    return r;
}
__device__ __forceinline__ void fma2(unsigned long long& d, unsigned long long a,
                                     unsigned long long b) {
    asm("fma.rn.f32x2 %0, %1, %2, %0;" : "+l"(d) : "l"(a), "l"(b));
}
__device__ __forceinline__ void upk2(unsigned long long v, float& lo, float& hi) {
    asm("mov.b64 {%0,%1},%2;" : "=f"(lo), "=f"(hi) : "l"(v));
}

// ---------------- CSR build ----------------
__global__ void k_hist(const int* __restrict__ dst, int* __restrict__ deg, int E, int N) {
    int i = blockIdx.x * blockDim.x + threadIdx.x;
    int e = i * 4;
    if (e + 3 < E) {
        int4 d4 = *reinterpret_cast<const int4*>(&dst[e]);
        if (d4.x >= 0 && d4.x < N) atomicAdd(&deg[d4.x], 1);
        if (d4.y >= 0 && d4.y < N) atomicAdd(&deg[d4.y], 1);
        if (d4.z >= 0 && d4.z < N) atomicAdd(&deg[d4.z], 1);
        if (d4.w >= 0 && d4.w < N) atomicAdd(&deg[d4.w], 1);
    } else {
        for (int k = e; k < E; k++) {
            int d = dst[k];
            if (d >= 0 && d < N) atomicAdd(&deg[d], 1);
        }
    }
}

__global__ void k_scan1(const int* __restrict__ deg, int* __restrict__ scantmp,
                        int* __restrict__ bsum, int n) {
    __shared__ int sh[512];
    int tid = threadIdx.x;
    int i = blockIdx.x * 512 + tid;
    int v = (i < n) ? deg[i] : 0;
    sh[tid] = v;
    __syncthreads();
#pragma unroll
    for (int off = 1; off < 512; off <<= 1) {
        int t = (tid >= off) ? sh[tid - off] : 0;
        __syncthreads();
        sh[tid] += t;
        __syncthreads();
    }
    if (i < n) scantmp[i] = sh[tid];
    if (tid == 511) bsum[blockIdx.x] = sh[511];
}

__global__ void k_scan2(int* bsum, int nb) {
    __shared__ int sh[256];
    int tid = threadIdx.x;
    int v = (tid < nb) ? bsum[tid] : 0;
    sh[tid] = v;
    __syncthreads();
#pragma unroll
    for (int off = 1; off < 256; off <<= 1) {
        int t = (tid >= off) ? sh[tid - off] : 0;
        __syncthreads();
        sh[tid] += t;
        __syncthreads();
    }
    if (tid < nb) bsum[tid] = sh[tid] - v;  // exclusive
}

__global__ void k_scan3(const int* __restrict__ scantmp, int* __restrict__ deg_cursor,
                        int* __restrict__ rowptr, const int* __restrict__ bsum,
                        int n, int E) {
    int i = blockIdx.x * blockDim.x + threadIdx.x;
    if (i < n) {
        int d = deg_cursor[i];
        int ex = scantmp[i] - d + bsum[i >> 9];
        rowptr[i] = ex;
        deg_cursor[i] = ex;   // cursor
    }
    if (i == 0) rowptr[n] = E;
}

__global__ void k_scatter(const int* __restrict__ src, const int* __restrict__ dst,
                          int* __restrict__ cursor, int* __restrict__ csrc, int E, int N) {
    int i = blockIdx.x * blockDim.x + threadIdx.x;
    int e = i * 4;
    if (e + 3 < E) {
        int4 s4 = *reinterpret_cast<const int4*>(&src[e]);
        int4 d4 = *reinterpret_cast<const int4*>(&dst[e]);
        if (d4.x >= 0 && d4.x < N) csrc[atomicAdd(&cursor[d4.x], 1)] = s4.x;
        if (d4.y >= 0 && d4.y < N) csrc[atomicAdd(&cursor[d4.y], 1)] = s4.y;
        if (d4.z >= 0 && d4.z < N) csrc[atomicAdd(&cursor[d4.z], 1)] = s4.z;
        if (d4.w >= 0 && d4.w < N) csrc[atomicAdd(&cursor[d4.w], 1)] = s4.w;
    } else {
        for (int k = e; k < E; k++) {
            int d = dst[k];
            if (d >= 0 && d < N) csrc[atomicAdd(&cursor[d], 1)] = src[k];
        }
    }
}

// ---------------- aggregation ----------------
// max over fp16 relu'd features (>=0, init 0 handles isolated nodes).
// Half-warp per edge-row: 16 lanes x LDG.64 (uint2 = 4 halves) = 128B fp16 row.
__global__ void k_agg_max64h(const uint2* __restrict__ feat, float4* __restrict__ out4,
                             const int* __restrict__ rowptr, const int* __restrict__ srcs,
                             int n) {
    int v = blockIdx.x * (blockDim.x >> 5) + (threadIdx.x >> 5);
    if (v >= n) return;
    int lane = threadIdx.x & 31;
    int half = lane >> 4, sub = lane & 15;
    int beg = rowptr[v], end = rowptr[v + 1];
    float4 a = make_float4(0.f, 0.f, 0.f, 0.f);
#pragma unroll 4
    for (int e = beg + half; e < end; e += 2) {
        int s = __ldg(&srcs[e]);
        uint2 t = feat[(size_t)s * 16 + sub];
        float2 f0 = __half22float2(*reinterpret_cast<const __half2*>(&t.x));
        float2 f1 = __half22float2(*reinterpret_cast<const __half2*>(&t.y));
        a.x = fmaxf(a.x, f0.x);
        a.y = fmaxf(a.y, f0.y);
        a.z = fmaxf(a.z, f1.x);
        a.w = fmaxf(a.w, f1.y);
    }
    a.x = fmaxf(a.x, __shfl_xor_sync(0xffffffffu, a.x, 16));
    a.y = fmaxf(a.y, __shfl_xor_sync(0xffffffffu, a.y, 16));
    a.z = fmaxf(a.z, __shfl_xor_sync(0xffffffffu, a.z, 16));
    a.w = fmaxf(a.w, __shfl_xor_sync(0xffffffffu, a.w, 16));
    if (half == 0) out4[(size_t)v * 16 + sub] = a;
}

// mean over fp16 32-dim features. Quarter-warp per edge-row: 8 lanes x uint2 = 64B row.
__global__ void k_agg_mean32h(const uint2* __restrict__ feat, float4* __restrict__ out4,
                              const int* __restrict__ rowptr, const int* __restrict__ srcs,
                              int n) {
    int v = blockIdx.x * (blockDim.x >> 5) + (threadIdx.x >> 5);
    if (v >= n) return;
    int lane = threadIdx.x & 31;
    int q = lane >> 3, sub = lane & 7;
    int beg = rowptr[v], end = rowptr[v + 1];
    float4 a = make_float4(0.f, 0.f, 0.f, 0.f);
#pragma unroll 4
    for (int e = beg + q; e < end; e += 4) {
        int s = __ldg(&srcs[e]);
        uint2 t = feat[(size_t)s * 8 + sub];
        float2 f0 = __half22float2(*reinterpret_cast<const __half2*>(&t.x));
        float2 f1 = __half22float2(*reinterpret_cast<const __half2*>(&t.y));
        a.x += f0.x; a.y += f0.y; a.z += f1.x; a.w += f1.y;
    }
#pragma unroll
    for (int off = 8; off <= 16; off <<= 1) {
        a.x += __shfl_xor_sync(0xffffffffu, a.x, off);
        a.y += __shfl_xor_sync(0xffffffffu, a.y, off);
        a.z += __shfl_xor_sync(0xffffffffu, a.z, off);
        a.w += __shfl_xor_sync(0xffffffffu, a.w, off);
    }
    if (q == 0) {
        float cnt = (float)(end - beg);
        float inv = 1.f / fmaxf(cnt, 1.f);
        a.x *= inv; a.y *= inv; a.z *= inv; a.w *= inv;
        out4[(size_t)v * 8 + sub] = a;
    }
}

// ---------------- node GEMM: direct-LDG activations, weights-only smem ----------------
// !ADD: out = [relu]( A@W + bias )   ADD: out = [relu]( out + A@W )
// HMODE 0: fp32 out.  1: fp16 out (into (ushort*)out).  2: fp32 out + fp16 copy to hcopy.
template <int IN, int OUT, bool RELU, bool ADD, int HMODE>
__global__ void __launch_bounds__(256, 3) k_gemm(const float4* __restrict__ A4,
                                                 const float* __restrict__ W,
                                                 const float* __restrict__ bias,
                                                 float* __restrict__ out,
                                                 unsigned short* __restrict__ hcopy,
                                                 int n) {
    constexpr int NPB = 128;
    constexpr int TJ = OUT / 8;
    constexpr int NP = TJ / 2;
    constexpr int V = IN / 4;
    extern __shared__ float sm[];
    float* sW = sm;
    float* sB = sm + IN * OUT;

    int tid = threadIdx.x;
    for (int i = tid; i < IN * OUT; i += 256) sW[i] = W[i];
    if (!ADD)
        for (int i = tid; i < OUT; i += 256) sB[i] = bias[i];
    __syncthreads();

    int jg = tid & 7;
    int ng = tid >> 3;
    int n0 = blockIdx.x * NPB + ng * 4;

    unsigned long long acc2[4][NP];
#pragma unroll
    for (int i = 0; i < 4; i++)
#pragma unroll
        for (int j = 0; j < NP; j++) acc2[i][j] = 0ull;

    for (int kq = 0; kq < IN; kq += 4) {
        float4 xv[4];
#pragma unroll
        for (int i = 0; i < 4; i++)
            xv[i] = (n0 + i < n) ? __ldg(&A4[(size_t)(n0 + i) * V + (kq >> 2)])
                                 : make_float4(0.f, 0.f, 0.f, 0.f);
#pragma unroll
        for (int h = 0; h < 2; h++) {
            unsigned long long wv0[NP], wv1[NP];
#pragma unroll
            for (int p = 0; p < NP; p += 2) {
                float4 w = *reinterpret_cast<const float4*>(
                    &sW[(kq + 2 * h) * OUT + jg * TJ + 2 * p]);
                wv0[p] = pk2(w.x, w.y);
                if (p + 1 < NP) wv0[p + 1] = pk2(w.z, w.w);
            }
#pragma unroll
            for (int p = 0; p < NP; p += 2) {
                float4 w = *reinterpret_cast<const float4*>(
                    &sW[(kq + 2 * h + 1) * OUT + jg * TJ + 2 * p]);
                wv1[p] = pk2(w.x, w.y);
                if (p + 1 < NP) wv1[p + 1] = pk2(w.z, w.w);
            }
#pragma unroll
            for (int i = 0; i < 4; i++) {
                float xlo = h ? xv[i].z : xv[i].x;
                float xhi = h ? xv[i].w : xv[i].y;
                unsigned long long a0 = pk2(xlo, xlo);
                unsigned long long a1 = pk2(xhi, xhi);
#pragma unroll
                for (int j = 0; j < NP; j++) {
                    fma2(acc2[i][j], a0, wv0[j]);
                    fma2(acc2[i][j], a1, wv1[j]);
                }
            }
        }
    }

#pragma unroll
    for (int i = 0; i < 4; i++) {
        int node = n0 + i;
        if (node < n) {
#pragma unroll
            for (int j = 0; j < NP; j++) {
                float lo, hi;
                upk2(acc2[i][j], lo, hi);
                float b0, b1;
                if (ADD) {
                    float2 old = *reinterpret_cast<const float2*>(
                        &out[(size_t)node * OUT + jg * TJ + 2 * j]);
                    b0 = old.x; b1 = old.y;
                } else {
                    b0 = sB[jg * TJ + 2 * j]; b1 = sB[jg * TJ + 2 * j + 1];
                }
                float v0 = lo + b0;
                float v1 = hi + b1;
                if (RELU) { v0 = fmaxf(v0, 0.f); v1 = fmaxf(v1, 0.f); }
                size_t off = (size_t)node * OUT + jg * TJ + 2 * j;
                if (HMODE == 1) {
                    *reinterpret_cast<__half2*>(
                        reinterpret_cast<unsigned short*>(out) + off) =
                        __floats2half2_rn(v0, v1);
                } else {
                    *reinterpret_cast<float2*>(&out[off]) = make_float2(v0, v1);
                    if (HMODE == 2)
                        *reinterpret_cast<__half2*>(hcopy + off) = __floats2half2_rn(v0, v1);
                }
            }
        }
    }
}

// ---------------- host launch ----------------
static inline int smem_bytes(int IN, int OUT) {
    return (IN * OUT + OUT) * (int)sizeof(float);
}

extern "C" void kernel_launch(void* const* d_in, const int* in_sizes, int n_in,
                              void* d_out, int out_size) {
    const float* x        = (const float*)d_in[0];
    const int*   ei       = (const int*)d_in[1];   // int32 (JAX x64 disabled)
    const float* W1_pool  = (const float*)d_in[2];
    const float* b1_pool  = (const float*)d_in[3];
    const float* W1_self  = (const float*)d_in[4];
    const float* W1_neigh = (const float*)d_in[5];
    const float* b1       = (const float*)d_in[6];
    const float* W2_pool  = (const float*)d_in[7];
    const float* b2_pool  = (const float*)d_in[8];
    const float* W2_self  = (const float*)d_in[9];
    const float* W2_neigh = (const float*)d_in[10];
    const float* b2       = (const float*)d_in[11];
    const float* W3_self  = (const float*)d_in[12];
    const float* W3_neigh = (const float*)d_in[13];
    const float* b3       = (const float*)d_in[14];

    int N = in_sizes[0] / 64;
    int E = in_sizes[1] / 2;
    if (N > MAXN) N = MAXN;
    if (E > MAXE) E = MAXE;

    const int* src = ei;        // row 0
    const int* dst = ei + E;    // row 1

    unsigned short* m;
    float *agg, *h1, *h2, *agg3;
    int *rowptr, *deg, *scantmp, *bsum, *csrc;
    cudaGetSymbolAddress((void**)&m, g_m);
    cudaGetSymbolAddress((void**)&agg, g_agg);
    cudaGetSymbolAddress((void**)&h1, g_h1);
    cudaGetSymbolAddress((void**)&h2, g_h2);
    cudaGetSymbolAddress((void**)&agg3, g_agg3);
    cudaGetSymbolAddress((void**)&rowptr, g_rowptr);
    cudaGetSymbolAddress((void**)&deg, g_deg);
    cudaGetSymbolAddress((void**)&scantmp, g_scantmp);
    cudaGetSymbolAddress((void**)&bsum, g_bsum);
    cudaGetSymbolAddress((void**)&csrc, g_csrc);

    static cudaStream_t sS = nullptr;
    static cudaEvent_t evFork, evCSR, evSelf1, evAdd1, evSelf2, evAdd2, evSelf3;
    if (!sS) {
        cudaStreamCreateWithFlags(&sS, cudaStreamNonBlocking);
        cudaEventCreateWithFlags(&evFork, cudaEventDisableTiming);
        cudaEventCreateWithFlags(&evCSR, cudaEventDisableTiming);
        cudaEventCreateWithFlags(&evSelf1, cudaEventDisableTiming);
        cudaEventCreateWithFlags(&evAdd1, cudaEventDisableTiming);
        cudaEventCreateWithFlags(&evAdd2, cudaEventDisableTiming);
        cudaEventCreateWithFlags(&evSelf2, cudaEventDisableTiming);
        cudaEventCreateWithFlags(&evSelf3, cudaEventDisableTiming);
    }

    int e4blocks = ((E + 3) / 4 + 255) / 256;
    int nblocks256 = (N + 255) / 256;
    int nblocks128 = (N + 127) / 128;
    int nbScan = (N + 511) / 512;
    int aggBlocks = (N + 7) / 8;

    // ---- fork ----
    cudaEventRecord(evFork, 0);
    cudaStreamWaitEvent(sS, evFork, 0);

    // Host call order: scan2 precedes the pool GEMM so ncu's capture slot
    // lands on the GEMM this time.
    cudaMemsetAsync(deg, 0, (size_t)N * sizeof(int), sS);
    k_hist<<<e4blocks, 256, 0, sS>>>(dst, deg, E, N);
    k_scan1<<<nbScan, 512, 0, sS>>>(deg, scantmp, bsum, N);
    k_scan2<<<1, 256, 0, sS>>>(bsum, nbScan);

    // main stream: layer-1 pool GEMM (fp16 output), concurrent with CSR
    k_gemm<64, 64, true, false, 1><<<nblocks128, 256, smem_bytes(64, 64)>>>(
        (const float4*)x, W1_pool, b1_pool, (float*)m, nullptr, N);

    k_scan3<<<nblocks256, 256, 0, sS>>>(scantmp, deg, rowptr, bsum, N, E);
    k_scatter<<<e4blocks, 256, 0, sS>>>(src, dst, deg, csrc, E, N);
    cudaEventRecord(evCSR, sS);
    k_gemm<64, 64, false, false, 0><<<nblocks128, 256, smem_bytes(64, 64), sS>>>(
        (const float4*)x, W1_self, b1, h1, nullptr, N);   // h1 partial
    cudaEventRecord(evSelf1, sS);

    // agg1 needs m (main) + CSR (side)
    cudaStreamWaitEvent(0, evCSR, 0);
    k_agg_max64h<<<aggBlocks, 256>>>((const uint2*)m, (float4*)agg, rowptr, csrc, N);
    cudaStreamWaitEvent(0, evSelf1, 0);
    k_gemm<64, 64, true, true, 0><<<nblocks128, 256, smem_bytes(64, 64)>>>(
        (const float4*)agg, W1_neigh, nullptr, h1, nullptr, N);  // h1 final
    cudaEventRecord(evAdd1, 0);

    // side stream: layer-2 self GEMM (needs h1)
    cudaStreamWaitEvent(sS, evAdd1, 0);
    k_gemm<64, 32, false, false, 0><<<nblocks128, 256, smem_bytes(64, 32), sS>>>(
        (const float4*)h1, W2_self, b2, h2, nullptr, N);   // h2 partial
    cudaEventRecord(evSelf2, sS);

    // main: layer-2 pool GEMM (fp16 out) + agg2
    k_gemm<64, 64, true, false, 1><<<nblocks128, 256, smem_bytes(64, 64)>>>(
        (const float4*)h1, W2_pool, b2_pool, (float*)m, nullptr, N);
    k_agg_max64h<<<aggBlocks, 256>>>((const uint2*)m, (float4*)agg, rowptr, csrc, N);
    cudaStreamWaitEvent(0, evSelf2, 0);
    // h2 final: fp32 + fp16 copy (reuses m buffer) for the mean gather
    k_gemm<64, 32, false, true, 2><<<nblocks128, 256, smem_bytes(64, 32)>>>(
        (const float4*)agg, W2_neigh, nullptr, h2, m, N);
    cudaEventRecord(evAdd2, 0);

    // side stream: layer-3 self GEMM (needs h2, fp32 — exact)
    cudaStreamWaitEvent(sS, evAdd2, 0);
    k_gemm<32, 32, false, false, 0><<<nblocks128, 256, smem_bytes(32, 32), sS>>>(
        (const float4*)h2, W3_self, b3, (float*)d_out, nullptr, N);  // out partial
    cudaEventRecord(evSelf3, sS);

    // main: agg3 (mean over fp16 h2 copy) + final add
    k_agg_mean32h<<<aggBlocks, 256>>>((const uint2*)m, (float4*)agg3, rowptr, csrc, N);
    cudaStreamWaitEvent(0, evSelf3, 0);
    k_gemm<32, 32, false, true, 0><<<nblocks128, 256, smem_bytes(32, 32)>>>(
        (const float4*)agg3, W3_neigh, nullptr, (float*)d_out, nullptr, N);  // out final
}

// round 15
// speedup vs baseline: 1.3596x; 1.1147x over previous
#include <cuda_runtime.h>
#include <cuda_fp16.h>
#include <cstdint>

#define MAXN 100000
#define MAXE 1600000

// ---------------- scratch (device globals; no allocs allowed) ----------------
__device__ unsigned short g_m[MAXN * 64];   // fp16: pool features / h2 copy
__device__ float g_agg[MAXN * 64];          // aggregated features (fp32)
__device__ float g_h1[MAXN * 64];
__device__ float g_h2[MAXN * 32];
__device__ float g_agg3[MAXN * 32];
__device__ int   g_rowptr[MAXN + 1];
__device__ int   g_deg[MAXN];
__device__ int   g_scantmp[MAXN];
__device__ int   g_bsum[1024];
__device__ int   g_csrc[MAXE];

// ---------------- f32x2 packed-FMA helpers ----------------
__device__ __forceinline__ unsigned long long pk2(float lo, float hi) {
    unsigned long long r;
    asm("mov.b64 %0,{%1,%2};" : "=l"(r) : "f"(lo), "f"(hi));
    return r;
}
__device__ __forceinline__ void fma2(unsigned long long& d, unsigned long long a,
                                     unsigned long long b) {
    asm("fma.rn.f32x2 %0, %1, %2, %0;" : "+l"(d) : "l"(a), "l"(b));
}
__device__ __forceinline__ void upk2(unsigned long long v, float& lo, float& hi) {
    asm("mov.b64 {%0,%1},%2;" : "=f"(lo), "=f"(hi) : "l"(v));
}

// ---------------- CSR build ----------------
__global__ void k_hist(const int* __restrict__ dst, int* __restrict__ deg, int E, int N) {
    int i = blockIdx.x * blockDim.x + threadIdx.x;
    int e = i * 4;
    if (e + 3 < E) {
        int4 d4 = *reinterpret_cast<const int4*>(&dst[e]);
        if (d4.x >= 0 && d4.x < N) atomicAdd(&deg[d4.x], 1);
        if (d4.y >= 0 && d4.y < N) atomicAdd(&deg[d4.y], 1);
        if (d4.z >= 0 && d4.z < N) atomicAdd(&deg[d4.z], 1);
        if (d4.w >= 0 && d4.w < N) atomicAdd(&deg[d4.w], 1);
    } else {
        for (int k = e; k < E; k++) {
            int d = dst[k];
            if (d >= 0 && d < N) atomicAdd(&deg[d], 1);
        }
    }
}

__global__ void k_scan1(const int* __restrict__ deg, int* __restrict__ scantmp,
                        int* __restrict__ bsum, int n) {
    __shared__ int sh[512];
    int tid = threadIdx.x;
    int i = blockIdx.x * 512 + tid;
    int v = (i < n) ? deg[i] : 0;
    sh[tid] = v;
    __syncthreads();
#pragma unroll
    for (int off = 1; off < 512; off <<= 1) {
        int t = (tid >= off) ? sh[tid - off] : 0;
        __syncthreads();
        sh[tid] += t;
        __syncthreads();
    }
    if (i < n) scantmp[i] = sh[tid];
    if (tid == 511) bsum[blockIdx.x] = sh[511];
}

__global__ void k_scan2(int* bsum, int nb) {
    __shared__ int sh[256];
    int tid = threadIdx.x;
    int v = (tid < nb) ? bsum[tid] : 0;
    sh[tid] = v;
    __syncthreads();
#pragma unroll
    for (int off = 1; off < 256; off <<= 1) {
        int t = (tid >= off) ? sh[tid - off] : 0;
        __syncthreads();
        sh[tid] += t;
        __syncthreads();
    }
    if (tid < nb) bsum[tid] = sh[tid] - v;  // exclusive
}

__global__ void k_scan3(const int* __restrict__ scantmp, int* __restrict__ deg_cursor,
                        int* __restrict__ rowptr, const int* __restrict__ bsum,
                        int n, int E) {
    int i = blockIdx.x * blockDim.x + threadIdx.x;
    if (i < n) {
        int d = deg_cursor[i];
        int ex = scantmp[i] - d + bsum[i >> 9];
        rowptr[i] = ex;
        deg_cursor[i] = ex;   // cursor
    }
    if (i == 0) rowptr[n] = E;
}

__global__ void k_scatter(const int* __restrict__ src, const int* __restrict__ dst,
                          int* __restrict__ cursor, int* __restrict__ csrc, int E, int N) {
    int i = blockIdx.x * blockDim.x + threadIdx.x;
    int e = i * 4;
    if (e + 3 < E) {
        int4 s4 = *reinterpret_cast<const int4*>(&src[e]);
        int4 d4 = *reinterpret_cast<const int4*>(&dst[e]);
        if (d4.x >= 0 && d4.x < N) csrc[atomicAdd(&cursor[d4.x], 1)] = s4.x;
        if (d4.y >= 0 && d4.y < N) csrc[atomicAdd(&cursor[d4.y], 1)] = s4.y;
        if (d4.z >= 0 && d4.z < N) csrc[atomicAdd(&cursor[d4.z], 1)] = s4.z;
        if (d4.w >= 0 && d4.w < N) csrc[atomicAdd(&cursor[d4.w], 1)] = s4.w;
    } else {
        for (int k = e; k < E; k++) {
            int d = dst[k];
            if (d >= 0 && d < N) csrc[atomicAdd(&cursor[d], 1)] = src[k];
        }
    }
}

// ---------------- aggregation ----------------
__global__ void k_agg_max64h(const uint2* __restrict__ feat, float4* __restrict__ out4,
                             const int* __restrict__ rowptr, const int* __restrict__ srcs,
                             int n) {
    int v = blockIdx.x * (blockDim.x >> 5) + (threadIdx.x >> 5);
    if (v >= n) return;
    int lane = threadIdx.x & 31;
    int half = lane >> 4, sub = lane & 15;
    int beg = rowptr[v], end = rowptr[v + 1];
    float4 a = make_float4(0.f, 0.f, 0.f, 0.f);
#pragma unroll 4
    for (int e = beg + half; e < end; e += 2) {
        int s = __ldg(&srcs[e]);
        uint2 t = feat[(size_t)s * 16 + sub];
        float2 f0 = __half22float2(*reinterpret_cast<const __half2*>(&t.x));
        float2 f1 = __half22float2(*reinterpret_cast<const __half2*>(&t.y));
        a.x = fmaxf(a.x, f0.x);
        a.y = fmaxf(a.y, f0.y);
        a.z = fmaxf(a.z, f1.x);
        a.w = fmaxf(a.w, f1.y);
    }
    a.x = fmaxf(a.x, __shfl_xor_sync(0xffffffffu, a.x, 16));
    a.y = fmaxf(a.y, __shfl_xor_sync(0xffffffffu, a.y, 16));
    a.z = fmaxf(a.z, __shfl_xor_sync(0xffffffffu, a.z, 16));
    a.w = fmaxf(a.w, __shfl_xor_sync(0xffffffffu, a.w, 16));
    if (half == 0) out4[(size_t)v * 16 + sub] = a;
}

__global__ void k_agg_mean32h(const uint2* __restrict__ feat, float4* __restrict__ out4,
                              const int* __restrict__ rowptr, const int* __restrict__ srcs,
                              int n) {
    int v = blockIdx.x * (blockDim.x >> 5) + (threadIdx.x >> 5);
    if (v >= n) return;
    int lane = threadIdx.x & 31;
    int q = lane >> 3, sub = lane & 7;
    int beg = rowptr[v], end = rowptr[v + 1];
    float4 a = make_float4(0.f, 0.f, 0.f, 0.f);
#pragma unroll 4
    for (int e = beg + q; e < end; e += 4) {
        int s = __ldg(&srcs[e]);
        uint2 t = feat[(size_t)s * 8 + sub];
        float2 f0 = __half22float2(*reinterpret_cast<const __half2*>(&t.x));
        float2 f1 = __half22float2(*reinterpret_cast<const __half2*>(&t.y));
        a.x += f0.x; a.y += f0.y; a.z += f1.x; a.w += f1.y;
    }
#pragma unroll
    for (int off = 8; off <= 16; off <<= 1) {
        a.x += __shfl_xor_sync(0xffffffffu, a.x, off);
        a.y += __shfl_xor_sync(0xffffffffu, a.y, off);
        a.z += __shfl_xor_sync(0xffffffffu, a.z, off);
        a.w += __shfl_xor_sync(0xffffffffu, a.w, off);
    }
    if (q == 0) {
        float cnt = (float)(end - beg);
        float inv = 1.f / fmaxf(cnt, 1.f);
        a.x *= inv; a.y *= inv; a.z *= inv; a.w *= inv;
        out4[(size_t)v * 8 + sub] = a;
    }
}

// ---------------- node GEMM: conflict-free per-jg weight slices ----------------
// Weights staged as sW[jg*SLICE + k*TJ + j], SLICE = IN*TJ+4 (16B pad): the 8 jg
// lanes start 4 words (mod 32) apart -> 16B weight LDS hit all 32 banks.
// !ADD: out = [relu]( A@W + bias )   ADD: out = [relu]( out + A@W )
// HMODE 0: fp32 out.  1: fp16 out.  2: fp32 out + fp16 copy to hcopy.
template <int IN, int OUT, bool RELU, bool ADD, int HMODE>
__global__ void __launch_bounds__(256, 3) k_gemm(const float4* __restrict__ A4,
                                                 const float* __restrict__ W,
                                                 const float* __restrict__ bias,
                                                 float* __restrict__ out,
                                                 unsigned short* __restrict__ hcopy,
                                                 int n) {
    constexpr int NPB = 128;
    constexpr int TJ = OUT / 8;
    constexpr int NP = TJ / 2;
    constexpr int V = IN / 4;
    constexpr int SLICE = IN * TJ + 4;   // per-jg slice stride (floats); SLICE%32==4
    extern __shared__ float sm[];
    float* sW = sm;              // 8*SLICE
    float* sB = sm + 8 * SLICE;  // OUT

    int tid = threadIdx.x;
    // stage W transposed into per-jg slices
    for (int i = tid; i < IN * OUT; i += 256) {
        int k = i / OUT, col = i % OUT;
        sW[(col / TJ) * SLICE + k * TJ + (col % TJ)] = W[i];
    }
    if (!ADD)
        for (int i = tid; i < OUT; i += 256) sB[i] = bias[i];
    __syncthreads();

    int jg = tid & 7;
    int ng = tid >> 3;
    int n0 = blockIdx.x * NPB + ng * 4;
    const float* sWj = sW + jg * SLICE;   // this thread's weight slice

    unsigned long long acc2[4][NP];
#pragma unroll
    for (int i = 0; i < 4; i++)
#pragma unroll
        for (int j = 0; j < NP; j++) acc2[i][j] = 0ull;

    for (int kq = 0; kq < IN; kq += 4) {
        float4 xv[4];
#pragma unroll
        for (int i = 0; i < 4; i++)
            xv[i] = (n0 + i < n) ? __ldg(&A4[(size_t)(n0 + i) * V + (kq >> 2)])
                                 : make_float4(0.f, 0.f, 0.f, 0.f);
#pragma unroll
        for (int h = 0; h < 2; h++) {
            unsigned long long wv0[NP], wv1[NP];
#pragma unroll
            for (int p = 0; p < NP; p += 2) {
                float4 w = *reinterpret_cast<const float4*>(
                    &sWj[(kq + 2 * h) * TJ + 2 * p]);
                wv0[p] = pk2(w.x, w.y);
                if (p + 1 < NP) wv0[p + 1] = pk2(w.z, w.w);
            }
#pragma unroll
            for (int p = 0; p < NP; p += 2) {
                float4 w = *reinterpret_cast<const float4*>(
                    &sWj[(kq + 2 * h + 1) * TJ + 2 * p]);
                wv1[p] = pk2(w.x, w.y);
                if (p + 1 < NP) wv1[p + 1] = pk2(w.z, w.w);
            }
#pragma unroll
            for (int i = 0; i < 4; i++) {
                float xlo = h ? xv[i].z : xv[i].x;
                float xhi = h ? xv[i].w : xv[i].y;
                unsigned long long a0 = pk2(xlo, xlo);
                unsigned long long a1 = pk2(xhi, xhi);
#pragma unroll
                for (int j = 0; j < NP; j++) {
                    fma2(acc2[i][j], a0, wv0[j]);
                    fma2(acc2[i][j], a1, wv1[j]);
                }
            }
        }
    }

#pragma unroll
    for (int i = 0; i < 4; i++) {
        int node = n0 + i;
        if (node < n) {
#pragma unroll
            for (int j = 0; j < NP; j++) {
                float lo, hi;
                upk2(acc2[i][j], lo, hi);
                float b0, b1;
                if (ADD) {
                    float2 old = *reinterpret_cast<const float2*>(
                        &out[(size_t)node * OUT + jg * TJ + 2 * j]);
                    b0 = old.x; b1 = old.y;
                } else {
                    b0 = sB[jg * TJ + 2 * j]; b1 = sB[jg * TJ + 2 * j + 1];
                }
                float v0 = lo + b0;
                float v1 = hi + b1;
                if (RELU) { v0 = fmaxf(v0, 0.f); v1 = fmaxf(v1, 0.f); }
                size_t off = (size_t)node * OUT + jg * TJ + 2 * j;
                if (HMODE == 1) {
                    *reinterpret_cast<__half2*>(
                        reinterpret_cast<unsigned short*>(out) + off) =
                        __floats2half2_rn(v0, v1);
                } else {
                    *reinterpret_cast<float2*>(&out[off]) = make_float2(v0, v1);
                    if (HMODE == 2)
                        *reinterpret_cast<__half2*>(hcopy + off) = __floats2half2_rn(v0, v1);
                }
            }
        }
    }
}

// ---------------- host launch ----------------
static inline int smem_bytes(int IN, int OUT) {
    int TJ = OUT / 8;
    return (8 * (IN * TJ + 4) + OUT) * (int)sizeof(float);
}

extern "C" void kernel_launch(void* const* d_in, const int* in_sizes, int n_in,
                              void* d_out, int out_size) {
    const float* x        = (const float*)d_in[0];
    const int*   ei       = (const int*)d_in[1];   // int32 (JAX x64 disabled)
    const float* W1_pool  = (const float*)d_in[2];
    const float* b1_pool  = (const float*)d_in[3];
    const float* W1_self  = (const float*)d_in[4];
    const float* W1_neigh = (const float*)d_in[5];
    const float* b1       = (const float*)d_in[6];
    const float* W2_pool  = (const float*)d_in[7];
    const float* b2_pool  = (const float*)d_in[8];
    const float* W2_self  = (const float*)d_in[9];
    const float* W2_neigh = (const float*)d_in[10];
    const float* b2       = (const float*)d_in[11];
    const float* W3_self  = (const float*)d_in[12];
    const float* W3_neigh = (const float*)d_in[13];
    const float* b3       = (const float*)d_in[14];

    int N = in_sizes[0] / 64;
    int E = in_sizes[1] / 2;
    if (N > MAXN) N = MAXN;
    if (E > MAXE) E = MAXE;

    const int* src = ei;        // row 0
    const int* dst = ei + E;    // row 1

    unsigned short* m;
    float *agg, *h1, *h2, *agg3;
    int *rowptr, *deg, *scantmp, *bsum, *csrc;
    cudaGetSymbolAddress((void**)&m, g_m);
    cudaGetSymbolAddress((void**)&agg, g_agg);
    cudaGetSymbolAddress((void**)&h1, g_h1);
    cudaGetSymbolAddress((void**)&h2, g_h2);
    cudaGetSymbolAddress((void**)&agg3, g_agg3);
    cudaGetSymbolAddress((void**)&rowptr, g_rowptr);
    cudaGetSymbolAddress((void**)&deg, g_deg);
    cudaGetSymbolAddress((void**)&scantmp, g_scantmp);
    cudaGetSymbolAddress((void**)&bsum, g_bsum);
    cudaGetSymbolAddress((void**)&csrc, g_csrc);

    static cudaStream_t sS = nullptr;
    static cudaEvent_t evFork, evCSR, evSelf1, evAdd1, evSelf2, evAdd2, evSelf3;
    if (!sS) {
        cudaStreamCreateWithFlags(&sS, cudaStreamNonBlocking);
        cudaEventCreateWithFlags(&evFork, cudaEventDisableTiming);
        cudaEventCreateWithFlags(&evCSR, cudaEventDisableTiming);
        cudaEventCreateWithFlags(&evSelf1, cudaEventDisableTiming);
        cudaEventCreateWithFlags(&evAdd1, cudaEventDisableTiming);
        cudaEventCreateWithFlags(&evAdd2, cudaEventDisableTiming);
        cudaEventCreateWithFlags(&evSelf2, cudaEventDisableTiming);
        cudaEventCreateWithFlags(&evSelf3, cudaEventDisableTiming);
    }

    int e4blocks = ((E + 3) / 4 + 255) / 256;
    int nblocks256 = (N + 255) / 256;
    int nblocks128 = (N + 127) / 128;
    int nbScan = (N + 511) / 512;
    int aggBlocks = (N + 7) / 8;

    // ---- fork ----
    cudaEventRecord(evFork, 0);
    cudaStreamWaitEvent(sS, evFork, 0);

    cudaMemsetAsync(deg, 0, (size_t)N * sizeof(int), sS);
    k_hist<<<e4blocks, 256, 0, sS>>>(dst, deg, E, N);
    k_scan1<<<nbScan, 512, 0, sS>>>(deg, scantmp, bsum, N);
    k_scan2<<<1, 256, 0, sS>>>(bsum, nbScan);

    // main stream: layer-1 pool GEMM (fp16 output), concurrent with CSR
    k_gemm<64, 64, true, false, 1><<<nblocks128, 256, smem_bytes(64, 64)>>>(
        (const float4*)x, W1_pool, b1_pool, (float*)m, nullptr, N);

    k_scan3<<<nblocks256, 256, 0, sS>>>(scantmp, deg, rowptr, bsum, N, E);
    k_scatter<<<e4blocks, 256, 0, sS>>>(src, dst, deg, csrc, E, N);
    cudaEventRecord(evCSR, sS);
    k_gemm<64, 64, false, false, 0><<<nblocks128, 256, smem_bytes(64, 64), sS>>>(
        (const float4*)x, W1_self, b1, h1, nullptr, N);   // h1 partial
    cudaEventRecord(evSelf1, sS);

    // agg1 needs m (main) + CSR (side)
    cudaStreamWaitEvent(0, evCSR, 0);
    k_agg_max64h<<<aggBlocks, 256>>>((const uint2*)m, (float4*)agg, rowptr, csrc, N);
    cudaStreamWaitEvent(0, evSelf1, 0);
    k_gemm<64, 64, true, true, 0><<<nblocks128, 256, smem_bytes(64, 64)>>>(
        (const float4*)agg, W1_neigh, nullptr, h1, nullptr, N);  // h1 final
    cudaEventRecord(evAdd1, 0);

    // side stream: layer-2 self GEMM (needs h1)
    cudaStreamWaitEvent(sS, evAdd1, 0);
    k_gemm<64, 32, false, false, 0><<<nblocks128, 256, smem_bytes(64, 32), sS>>>(
        (const float4*)h1, W2_self, b2, h2, nullptr, N);   // h2 partial
    cudaEventRecord(evSelf2, sS);

    // main: layer-2 pool GEMM (fp16 out) + agg2
    k_gemm<64, 64, true, false, 1><<<nblocks128, 256, smem_bytes(64, 64)>>>(
        (const float4*)h1, W2_pool, b2_pool, (float*)m, nullptr, N);
    k_agg_max64h<<<aggBlocks, 256>>>((const uint2*)m, (float4*)agg, rowptr, csrc, N);
    cudaStreamWaitEvent(0, evSelf2, 0);
    // h2 final: fp32 + fp16 copy (reuses m buffer) for the mean gather
    k_gemm<64, 32, false, true, 2><<<nblocks128, 256, smem_bytes(64, 32)>>>(
        (const float4*)agg, W2_neigh, nullptr, h2, m, N);
    cudaEventRecord(evAdd2, 0);

    // side stream: layer-3 self GEMM (needs h2, fp32 — exact)
    cudaStreamWaitEvent(sS, evAdd2, 0);
    k_gemm<32, 32, false, false, 0><<<nblocks128, 256, smem_bytes(32, 32), sS>>>(
        (const float4*)h2, W3_self, b3, (float*)d_out, nullptr, N);  // out partial
    cudaEventRecord(evSelf3, sS);

    // main: agg3 (mean over fp16 h2 copy) + final add
    k_agg_mean32h<<<aggBlocks, 256>>>((const uint2*)m, (float4*)agg3, rowptr, csrc, N);
    cudaStreamWaitEvent(0, evSelf3, 0);
    k_gemm<32, 32, false, true, 0><<<nblocks128, 256, smem_bytes(32, 32)>>>(
        (const float4*)agg3, W3_neigh, nullptr, (float*)d_out, nullptr, N);  // out final
}

// round 17
// speedup vs baseline: 1.3888x; 1.0215x over previous
#include <cuda_runtime.h>
#include <cuda_fp16.h>
#include <cstdint>

#define MAXN 100000
#define MAXE 1600000

// ---------------- scratch (device globals; no allocs allowed) ----------------
__device__ unsigned short g_m[MAXN * 64];   // fp16: pool features / h2 copy
__device__ float g_agg[MAXN * 64];          // aggregated features (fp32)
__device__ float g_h1[MAXN * 64];
__device__ float g_h2[MAXN * 32];
__device__ float g_agg3[MAXN * 32];
__device__ int   g_rowptr[MAXN + 1];
__device__ int   g_deg[MAXN];
__device__ int   g_scantmp[MAXN];
__device__ int   g_bsum[1024];
__device__ int   g_csrc[MAXE];

// ---------------- f32x2 packed-FMA helpers ----------------
__device__ __forceinline__ unsigned long long pk2(float lo, float hi) {
    unsigned long long r;
    asm("mov.b64 %0,{%1,%2};" : "=l"(r) : "f"(lo), "f"(hi));
    return r;
}
__device__ __forceinline__ void fma2(unsigned long long& d, unsigned long long a,
                                     unsigned long long b) {
    asm("fma.rn.f32x2 %0, %1, %2, %0;" : "+l"(d) : "l"(a), "l"(b));
}
__device__ __forceinline__ void upk2(unsigned long long v, float& lo, float& hi) {
    asm("mov.b64 {%0,%1},%2;" : "=f"(lo), "=f"(hi) : "l"(v));
}

// ---------------- CSR build ----------------
__global__ void k_hist(const int* __restrict__ dst, int* __restrict__ deg, int E, int N) {
    int i = blockIdx.x * blockDim.x + threadIdx.x;
    int e = i * 4;
    if (e + 3 < E) {
        int4 d4 = *reinterpret_cast<const int4*>(&dst[e]);
        if (d4.x >= 0 && d4.x < N) atomicAdd(&deg[d4.x], 1);
        if (d4.y >= 0 && d4.y < N) atomicAdd(&deg[d4.y], 1);
        if (d4.z >= 0 && d4.z < N) atomicAdd(&deg[d4.z], 1);
        if (d4.w >= 0 && d4.w < N) atomicAdd(&deg[d4.w], 1);
    } else {
        for (int k = e; k < E; k++) {
            int d = dst[k];
            if (d >= 0 && d < N) atomicAdd(&deg[d], 1);
        }
    }
}

__global__ void k_scan1(const int* __restrict__ deg, int* __restrict__ scantmp,
                        int* __restrict__ bsum, int n) {
    __shared__ int sh[512];
    int tid = threadIdx.x;
    int i = blockIdx.x * 512 + tid;
    int v = (i < n) ? deg[i] : 0;
    sh[tid] = v;
    __syncthreads();
#pragma unroll
    for (int off = 1; off < 512; off <<= 1) {
        int t = (tid >= off) ? sh[tid - off] : 0;
        __syncthreads();
        sh[tid] += t;
        __syncthreads();
    }
    if (i < n) scantmp[i] = sh[tid];
    if (tid == 511) bsum[blockIdx.x] = sh[511];
}

__global__ void k_scan2(int* bsum, int nb) {
    __shared__ int sh[256];
    int tid = threadIdx.x;
    int v = (tid < nb) ? bsum[tid] : 0;
    sh[tid] = v;
    __syncthreads();
#pragma unroll
    for (int off = 1; off < 256; off <<= 1) {
        int t = (tid >= off) ? sh[tid - off] : 0;
        __syncthreads();
        sh[tid] += t;
        __syncthreads();
    }
    if (tid < nb) bsum[tid] = sh[tid] - v;  // exclusive
}

__global__ void k_scan3(const int* __restrict__ scantmp, int* __restrict__ deg_cursor,
                        int* __restrict__ rowptr, const int* __restrict__ bsum,
                        int n, int E) {
    int i = blockIdx.x * blockDim.x + threadIdx.x;
    if (i < n) {
        int d = deg_cursor[i];
        int ex = scantmp[i] - d + bsum[i >> 9];
        rowptr[i] = ex;
        deg_cursor[i] = ex;   // cursor
    }
    if (i == 0) rowptr[n] = E;
}

__global__ void k_scatter(const int* __restrict__ src, const int* __restrict__ dst,
                          int* __restrict__ cursor, int* __restrict__ csrc, int E, int N) {
    int i = blockIdx.x * blockDim.x + threadIdx.x;
    int e = i * 4;
    if (e + 3 < E) {
        int4 s4 = *reinterpret_cast<const int4*>(&src[e]);
        int4 d4 = *reinterpret_cast<const int4*>(&dst[e]);
        if (d4.x >= 0 && d4.x < N) csrc[atomicAdd(&cursor[d4.x], 1)] = s4.x;
        if (d4.y >= 0 && d4.y < N) csrc[atomicAdd(&cursor[d4.y], 1)] = s4.y;
        if (d4.z >= 0 && d4.z < N) csrc[atomicAdd(&cursor[d4.z], 1)] = s4.z;
        if (d4.w >= 0 && d4.w < N) csrc[atomicAdd(&cursor[d4.w], 1)] = s4.w;
    } else {
        for (int k = e; k < E; k++) {
            int d = dst[k];
            if (d >= 0 && d < N) csrc[atomicAdd(&cursor[d], 1)] = src[k];
        }
    }
}

// ---------------- aggregation ----------------
__global__ void k_agg_max64h(const uint2* __restrict__ feat, float4* __restrict__ out4,
                             const int* __restrict__ rowptr, const int* __restrict__ srcs,
                             int n) {
    int v = blockIdx.x * (blockDim.x >> 5) + (threadIdx.x >> 5);
    if (v >= n) return;
    int lane = threadIdx.x & 31;
    int half = lane >> 4, sub = lane & 15;
    int beg = rowptr[v], end = rowptr[v + 1];
    float4 a = make_float4(0.f, 0.f, 0.f, 0.f);
#pragma unroll 4
    for (int e = beg + half; e < end; e += 2) {
        int s = __ldg(&srcs[e]);
        uint2 t = feat[(size_t)s * 16 + sub];
        float2 f0 = __half22float2(*reinterpret_cast<const __half2*>(&t.x));
        float2 f1 = __half22float2(*reinterpret_cast<const __half2*>(&t.y));
        a.x = fmaxf(a.x, f0.x);
        a.y = fmaxf(a.y, f0.y);
        a.z = fmaxf(a.z, f1.x);
        a.w = fmaxf(a.w, f1.y);
    }
    a.x = fmaxf(a.x, __shfl_xor_sync(0xffffffffu, a.x, 16));
    a.y = fmaxf(a.y, __shfl_xor_sync(0xffffffffu, a.y, 16));
    a.z = fmaxf(a.z, __shfl_xor_sync(0xffffffffu, a.z, 16));
    a.w = fmaxf(a.w, __shfl_xor_sync(0xffffffffu, a.w, 16));
    if (half == 0) out4[(size_t)v * 16 + sub] = a;
}

__global__ void k_agg_mean32h(const uint2* __restrict__ feat, float4* __restrict__ out4,
                              const int* __restrict__ rowptr, const int* __restrict__ srcs,
                              int n) {
    int v = blockIdx.x * (blockDim.x >> 5) + (threadIdx.x >> 5);
    if (v >= n) return;
    int lane = threadIdx.x & 31;
    int q = lane >> 3, sub = lane & 7;
    int beg = rowptr[v], end = rowptr[v + 1];
    float4 a = make_float4(0.f, 0.f, 0.f, 0.f);
#pragma unroll 4
    for (int e = beg + q; e < end; e += 4) {
        int s = __ldg(&srcs[e]);
        uint2 t = feat[(size_t)s * 8 + sub];
        float2 f0 = __half22float2(*reinterpret_cast<const __half2*>(&t.x));
        float2 f1 = __half22float2(*reinterpret_cast<const __half2*>(&t.y));
        a.x += f0.x; a.y += f0.y; a.z += f1.x; a.w += f1.y;
    }
#pragma unroll
    for (int off = 8; off <= 16; off <<= 1) {
        a.x += __shfl_xor_sync(0xffffffffu, a.x, off);
        a.y += __shfl_xor_sync(0xffffffffu, a.y, off);
        a.z += __shfl_xor_sync(0xffffffffu, a.z, off);
        a.w += __shfl_xor_sync(0xffffffffu, a.w, off);
    }
    if (q == 0) {
        float cnt = (float)(end - beg);
        float inv = 1.f / fmaxf(cnt, 1.f);
        a.x *= inv; a.y *= inv; a.z *= inv; a.w *= inv;
        out4[(size_t)v * 8 + sub] = a;
    }
}

// ---------------- persistent node GEMM: conflict-free slices, grid-stride tiles ----
// Weights staged ONCE per block into per-jg slices (SLICE%32==4 -> conflict-free),
// then the block loops over 128-node tiles.
// !ADD: out = [relu]( A@W + bias )   ADD: out = [relu]( out + A@W )
// HMODE 0: fp32 out.  1: fp16 out.  2: fp32 out + fp16 copy to hcopy.
template <int IN, int OUT, bool RELU, bool ADD, int HMODE>
__global__ void __launch_bounds__(256, 3) k_gemm(const float4* __restrict__ A4,
                                                 const float* __restrict__ W,
                                                 const float* __restrict__ bias,
                                                 float* __restrict__ out,
                                                 unsigned short* __restrict__ hcopy,
                                                 int n) {
    constexpr int NPB = 128;
    constexpr int TJ = OUT / 8;
    constexpr int NP = TJ / 2;
    constexpr int V = IN / 4;
    constexpr int SLICE = IN * TJ + 4;   // per-jg slice stride; SLICE%32==4
    extern __shared__ float sm[];
    float* sW = sm;              // 8*SLICE
    float* sB = sm + 8 * SLICE;  // OUT

    int tid = threadIdx.x;
    for (int i = tid; i < IN * OUT; i += 256) {
        int k = i / OUT, col = i % OUT;
        sW[(col / TJ) * SLICE + k * TJ + (col % TJ)] = W[i];
    }
    if (!ADD)
        for (int i = tid; i < OUT; i += 256) sB[i] = bias[i];
    __syncthreads();

    int jg = tid & 7;
    int ng = tid >> 3;
    const float* sWj = sW + jg * SLICE;
    int ntiles = (n + NPB - 1) / NPB;

    for (int tile = blockIdx.x; tile < ntiles; tile += gridDim.x) {
        int n0 = tile * NPB + ng * 4;

        unsigned long long acc2[4][NP];
#pragma unroll
        for (int i = 0; i < 4; i++)
#pragma unroll
            for (int j = 0; j < NP; j++) acc2[i][j] = 0ull;

        for (int kq = 0; kq < IN; kq += 4) {
            float4 xv[4];
#pragma unroll
            for (int i = 0; i < 4; i++)
                xv[i] = (n0 + i < n) ? __ldg(&A4[(size_t)(n0 + i) * V + (kq >> 2)])
                                     : make_float4(0.f, 0.f, 0.f, 0.f);
#pragma unroll
            for (int h = 0; h < 2; h++) {
                unsigned long long wv0[NP], wv1[NP];
#pragma unroll
                for (int p = 0; p < NP; p += 2) {
                    float4 w = *reinterpret_cast<const float4*>(
                        &sWj[(kq + 2 * h) * TJ + 2 * p]);
                    wv0[p] = pk2(w.x, w.y);
                    if (p + 1 < NP) wv0[p + 1] = pk2(w.z, w.w);
                }
#pragma unroll
                for (int p = 0; p < NP; p += 2) {
                    float4 w = *reinterpret_cast<const float4*>(
                        &sWj[(kq + 2 * h + 1) * TJ + 2 * p]);
                    wv1[p] = pk2(w.x, w.y);
                    if (p + 1 < NP) wv1[p + 1] = pk2(w.z, w.w);
                }
#pragma unroll
                for (int i = 0; i < 4; i++) {
                    float xlo = h ? xv[i].z : xv[i].x;
                    float xhi = h ? xv[i].w : xv[i].y;
                    unsigned long long a0 = pk2(xlo, xlo);
                    unsigned long long a1 = pk2(xhi, xhi);
#pragma unroll
                    for (int j = 0; j < NP; j++) {
                        fma2(acc2[i][j], a0, wv0[j]);
                        fma2(acc2[i][j], a1, wv1[j]);
                    }
                }
            }
        }

#pragma unroll
        for (int i = 0; i < 4; i++) {
            int node = n0 + i;
            if (node < n) {
#pragma unroll
                for (int j = 0; j < NP; j++) {
                    float lo, hi;
                    upk2(acc2[i][j], lo, hi);
                    float b0, b1;
                    if (ADD) {
                        float2 old = *reinterpret_cast<const float2*>(
                            &out[(size_t)node * OUT + jg * TJ + 2 * j]);
                        b0 = old.x; b1 = old.y;
                    } else {
                        b0 = sB[jg * TJ + 2 * j]; b1 = sB[jg * TJ + 2 * j + 1];
                    }
                    float v0 = lo + b0;
                    float v1 = hi + b1;
                    if (RELU) { v0 = fmaxf(v0, 0.f); v1 = fmaxf(v1, 0.f); }
                    size_t off = (size_t)node * OUT + jg * TJ + 2 * j;
                    if (HMODE == 1) {
                        *reinterpret_cast<__half2*>(
                            reinterpret_cast<unsigned short*>(out) + off) =
                            __floats2half2_rn(v0, v1);
                    } else {
                        *reinterpret_cast<float2*>(&out[off]) = make_float2(v0, v1);
                        if (HMODE == 2)
                            *reinterpret_cast<__half2*>(hcopy + off) =
                                __floats2half2_rn(v0, v1);
                    }
                }
            }
        }
    }
}

// ---------------- host launch ----------------
static inline int smem_bytes(int IN, int OUT) {
    int TJ = OUT / 8;
    return (8 * (IN * TJ + 4) + OUT) * (int)sizeof(float);
}

extern "C" void kernel_launch(void* const* d_in, const int* in_sizes, int n_in,
                              void* d_out, int out_size) {
    const float* x        = (const float*)d_in[0];
    const int*   ei       = (const int*)d_in[1];   // int32 (JAX x64 disabled)
    const float* W1_pool  = (const float*)d_in[2];
    const float* b1_pool  = (const float*)d_in[3];
    const float* W1_self  = (const float*)d_in[4];
    const float* W1_neigh = (const float*)d_in[5];
    const float* b1       = (const float*)d_in[6];
    const float* W2_pool  = (const float*)d_in[7];
    const float* b2_pool  = (const float*)d_in[8];
    const float* W2_self  = (const float*)d_in[9];
    const float* W2_neigh = (const float*)d_in[10];
    const float* b2       = (const float*)d_in[11];
    const float* W3_self  = (const float*)d_in[12];
    const float* W3_neigh = (const float*)d_in[13];
    const float* b3       = (const float*)d_in[14];

    int N = in_sizes[0] / 64;
    int E = in_sizes[1] / 2;
    if (N > MAXN) N = MAXN;
    if (E > MAXE) E = MAXE;

    const int* src = ei;        // row 0
    const int* dst = ei + E;    // row 1

    unsigned short* m;
    float *agg, *h1, *h2, *agg3;
    int *rowptr, *deg, *scantmp, *bsum, *csrc;
    cudaGetSymbolAddress((void**)&m, g_m);
    cudaGetSymbolAddress((void**)&agg, g_agg);
    cudaGetSymbolAddress((void**)&h1, g_h1);
    cudaGetSymbolAddress((void**)&h2, g_h2);
    cudaGetSymbolAddress((void**)&agg3, g_agg3);
    cudaGetSymbolAddress((void**)&rowptr, g_rowptr);
    cudaGetSymbolAddress((void**)&deg, g_deg);
    cudaGetSymbolAddress((void**)&scantmp, g_scantmp);
    cudaGetSymbolAddress((void**)&bsum, g_bsum);
    cudaGetSymbolAddress((void**)&csrc, g_csrc);

    static cudaStream_t sS = nullptr;
    static cudaEvent_t evFork, evCSR, evSelf1, evAdd1, evSelf2, evAdd2, evSelf3;
    static int gemmGrid = 0;
    if (!sS) {
        cudaStreamCreateWithFlags(&sS, cudaStreamNonBlocking);
        cudaEventCreateWithFlags(&evFork, cudaEventDisableTiming);
        cudaEventCreateWithFlags(&evCSR, cudaEventDisableTiming);
        cudaEventCreateWithFlags(&evSelf1, cudaEventDisableTiming);
        cudaEventCreateWithFlags(&evAdd1, cudaEventDisableTiming);
        cudaEventCreateWithFlags(&evAdd2, cudaEventDisableTiming);
        cudaEventCreateWithFlags(&evSelf2, cudaEventDisableTiming);
        cudaEventCreateWithFlags(&evSelf3, cudaEventDisableTiming);
        int sms = 148, dev = 0;
        cudaGetDevice(&dev);
        cudaDeviceGetAttribute(&sms, cudaDevAttrMultiProcessorCount, dev);
        gemmGrid = sms * 3;   // 3 blocks/SM residency, exactly 1 wave
    }

    int e4blocks = ((E + 3) / 4 + 255) / 256;
    int nblocks256 = (N + 255) / 256;
    int nbScan = (N + 511) / 512;
    int aggBlocks = (N + 7) / 8;
    int ntiles = (N + 127) / 128;
    int gGrid = gemmGrid < ntiles ? gemmGrid : ntiles;

    // ---- fork ----
    cudaEventRecord(evFork, 0);
    cudaStreamWaitEvent(sS, evFork, 0);

    cudaMemsetAsync(deg, 0, (size_t)N * sizeof(int), sS);
    k_hist<<<e4blocks, 256, 0, sS>>>(dst, deg, E, N);
    k_scan1<<<nbScan, 512, 0, sS>>>(deg, scantmp, bsum, N);
    k_scan2<<<1, 256, 0, sS>>>(bsum, nbScan);

    // main stream: layer-1 pool GEMM (fp16 output), concurrent with CSR
    k_gemm<64, 64, true, false, 1><<<gGrid, 256, smem_bytes(64, 64)>>>(
        (const float4*)x, W1_pool, b1_pool, (float*)m, nullptr, N);

    k_scan3<<<nblocks256, 256, 0, sS>>>(scantmp, deg, rowptr, bsum, N, E);
    k_scatter<<<e4blocks, 256, 0, sS>>>(src, dst, deg, csrc, E, N);
    cudaEventRecord(evCSR, sS);
    k_gemm<64, 64, false, false, 0><<<gGrid, 256, smem_bytes(64, 64), sS>>>(
        (const float4*)x, W1_self, b1, h1, nullptr, N);   // h1 partial
    cudaEventRecord(evSelf1, sS);

    // agg1 needs m (main) + CSR (side)
    cudaStreamWaitEvent(0, evCSR, 0);
    k_agg_max64h<<<aggBlocks, 256>>>((const uint2*)m, (float4*)agg, rowptr, csrc, N);
    cudaStreamWaitEvent(0, evSelf1, 0);
    k_gemm<64, 64, true, true, 0><<<gGrid, 256, smem_bytes(64, 64)>>>(
        (const float4*)agg, W1_neigh, nullptr, h1, nullptr, N);  // h1 final
    cudaEventRecord(evAdd1, 0);

    // side stream: layer-2 self GEMM (needs h1)
    cudaStreamWaitEvent(sS, evAdd1, 0);
    k_gemm<64, 32, false, false, 0><<<gGrid, 256, smem_bytes(64, 32), sS>>>(
        (const float4*)h1, W2_self, b2, h2, nullptr, N);   // h2 partial
    cudaEventRecord(evSelf2, sS);

    // main: layer-2 pool GEMM (fp16 out) + agg2
    k_gemm<64, 64, true, false, 1><<<gGrid, 256, smem_bytes(64, 64)>>>(
        (const float4*)h1, W2_pool, b2_pool, (float*)m, nullptr, N);
    k_agg_max64h<<<aggBlocks, 256>>>((const uint2*)m, (float4*)agg, rowptr, csrc, N);
    cudaStreamWaitEvent(0, evSelf2, 0);
    // h2 final: fp32 + fp16 copy (reuses m buffer) for the mean gather
    k_gemm<64, 32, false, true, 2><<<gGrid, 256, smem_bytes(64, 32)>>>(
        (const float4*)agg, W2_neigh, nullptr, h2, m, N);
    cudaEventRecord(evAdd2, 0);

    // side stream: layer-3 self GEMM (needs h2, fp32 — exact)
    cudaStreamWaitEvent(sS, evAdd2, 0);
    k_gemm<32, 32, false, false, 0><<<gGrid, 256, smem_bytes(32, 32), sS>>>(
        (const float4*)h2, W3_self, b3, (float*)d_out, nullptr, N);  // out partial
    cudaEventRecord(evSelf3, sS);

    // main: agg3 (mean over fp16 h2 copy) + final add
    k_agg_mean32h<<<aggBlocks, 256>>>((const uint2*)m, (float4*)agg3, rowptr, csrc, N);
    cudaStreamWaitEvent(0, evSelf3, 0);
    k_gemm<32, 32, false, true, 0><<<gGrid, 256, smem_bytes(32, 32)>>>(
        (const float4*)agg3, W3_neigh, nullptr, (float*)d_out, nullptr, N);  // out final
}